// round 7
// baseline (speedup 1.0000x reference)
#include <cuda_runtime.h>
#include <math.h>

// ---------------- problem constants ----------------
#define NMAX 50000
#define EMAX 800000
#define CH   128
#define LOUT 64

// ---------------- device scratch ----------------
struct alignas(8) Edge { int s; float nm; };
__device__ float g_deg[NMAX];        // zeroed at end of each call (scan)
__device__ float g_dis[NMAX];
__device__ float g_selfnorm[NMAX];
__device__ int   g_count[NMAX];      // zeroed at end of each call (scan)
__device__ int   g_rowstart[NMAX + 1];
__device__ int   g_cursor[NMAX];
__device__ Edge  g_csr[EMAX];
__device__ float g_agg[(size_t)NMAX * CH];   // aggregation output (GEMM input)
__device__ float g_act[(size_t)NMAX * CH];   // GEMM output (raw, pre-BN)
__device__ float g_bnsum[CH];        // zeroed after use (bnparam); zero-init at load
__device__ float g_bnsq[CH];
__device__ float g_scale[CH];
__device__ float g_shift[CH];

// ---------------- helpers ----------------
__device__ __forceinline__ bool idx_is64(const void* ei) {
    const int* w = (const int*)ei;
    return ((w[1] | w[3] | w[5] | w[7] | w[9]) == 0);
}
__device__ __forceinline__ int fetch_idx(const void* p, long long i, bool is64) {
    if (is64) return (int)((const long long*)p)[i];
    return ((const int*)p)[i];
}

// ---------------- degree + count accumulation ----------------
__global__ void k_deg(const void* ei, const float* __restrict__ ew, int E) {
    int e = blockIdx.x * blockDim.x + threadIdx.x;
    if (e >= E) return;
    bool is64 = idx_is64(ei);
    int d = fetch_idx(ei, (long long)E + e, is64);
    atomicAdd(&g_deg[d], ew[e]);
    atomicAdd(&g_count[d], 1);
}

// single block: dis/selfnorm from deg+1 (self loop), scan count -> rowstart/cursor,
// re-zero deg & count so the next call starts clean.
__global__ void k_scan_dis(int N) {
    __shared__ int ssum[1024];
    int t = threadIdx.x;
    int chunk = (N + 1023) / 1024;
    int lo = t * chunk;
    int hi = min(lo + chunk, N);
    int s = 0;
    for (int i = lo; i < hi; i++) {
        s += g_count[i];
        float d = rsqrtf(g_deg[i] + 1.0f);   // +1: self-loop weight
        g_dis[i] = d;
        g_selfnorm[i] = d * d;
        g_deg[i] = 0.f;
    }
    ssum[t] = s;
    __syncthreads();
    for (int off = 1; off < 1024; off <<= 1) {
        int v = (t >= off) ? ssum[t - off] : 0;
        __syncthreads();
        ssum[t] += v;
        __syncthreads();
    }
    int base = (t == 0) ? 0 : ssum[t - 1];
    for (int i = lo; i < hi; i++) {
        g_rowstart[i] = base;
        g_cursor[i]   = base;
        base += g_count[i];
        g_count[i] = 0;
    }
    if (t == 1023) g_rowstart[N] = ssum[1023];
}

__global__ void k_fill(const void* ei, const float* __restrict__ ew, int E) {
    int e = blockIdx.x * blockDim.x + threadIdx.x;
    if (e >= E) return;
    bool is64 = idx_is64(ei);
    int s = fetch_idx(ei, e, is64);
    int d = fetch_idx(ei, (long long)E + e, is64);
    float nm = g_dis[s] * ew[e] * g_dis[d];
    int pos = atomicAdd(&g_cursor[d], 1);
    Edge ed; ed.s = s; ed.nm = nm;
    g_csr[pos] = ed;
}

// ---------------- aggregation: out = S * f(act), barrier-free, warp per node ----
// f = BN ? per-channel scale/shift + relu : identity (fused on load; FMA-pipe slack
// under the L2-gather latency makes this nearly free).
template<bool BN>
__global__ void k_agg(const float* __restrict__ act, float* __restrict__ out, int N) {
    int gw   = (blockIdx.x * blockDim.x + threadIdx.x) >> 5;
    int lane = threadIdx.x & 31;
    if (gw >= N) return;

    float4 sc, sh;
    if (BN) {
        sc = *(const float4*)&g_scale[lane * 4];
        sh = *(const float4*)&g_shift[lane * 4];
    }
    float sn = g_selfnorm[gw];
    float4 tv = *(const float4*)&act[(size_t)gw * CH + lane * 4];
    if (BN) {
        tv.x = fmaxf(fmaf(tv.x, sc.x, sh.x), 0.f);
        tv.y = fmaxf(fmaf(tv.y, sc.y, sh.y), 0.f);
        tv.z = fmaxf(fmaf(tv.z, sc.z, sh.z), 0.f);
        tv.w = fmaxf(fmaf(tv.w, sc.w, sh.w), 0.f);
    }
    float a0 = sn * tv.x, a1 = sn * tv.y, a2 = sn * tv.z, a3 = sn * tv.w;

    int r0 = g_rowstart[gw], r1 = g_rowstart[gw + 1];
    #pragma unroll 4
    for (int e = r0; e < r1; e++) {
        Edge ed = g_csr[e];
        float nm = ed.nm;
        float4 v = *(const float4*)&act[(size_t)ed.s * CH + lane * 4];
        if (BN) {
            v.x = fmaxf(fmaf(v.x, sc.x, sh.x), 0.f);
            v.y = fmaxf(fmaf(v.y, sc.y, sh.y), 0.f);
            v.z = fmaxf(fmaf(v.z, sc.z, sh.z), 0.f);
            v.w = fmaxf(fmaf(v.w, sc.w, sh.w), 0.f);
        }
        a0 = fmaf(nm, v.x, a0); a1 = fmaf(nm, v.y, a1);
        a2 = fmaf(nm, v.z, a2); a3 = fmaf(nm, v.w, a3);
    }
    *(float4*)&out[(size_t)gw * CH + lane * 4] = make_float4(a0, a1, a2, a3);
}

// ---------------- SGEMM: out = A[N,128] @ W[128,COUT]  (pure; R3-measured config) ----
// No bias (GCN bias cancels exactly in the following BatchNorm), no stats epilogue,
// no occupancy cap — keep registers at the natural 127.
template<int COUT>
__global__ __launch_bounds__(256) void k_gemm(const float* __restrict__ A,
                                              const float* __restrict__ W,
                                              float* __restrict__ out, int N) {
    constexpr int BM = 128, BK = 32, TN = COUT / 16;
    __shared__ float As[BK][BM + 4];
    __shared__ float Bs[BK][COUT];
    int tid = threadIdx.x;
    int brow = blockIdx.x * BM;
    int ty = tid >> 4, tx = tid & 15;

    float acc[8][TN];
    #pragma unroll
    for (int i = 0; i < 8; i++)
        #pragma unroll
        for (int j = 0; j < TN; j++) acc[i][j] = 0.f;

    for (int k0 = 0; k0 < 128; k0 += BK) {
        #pragma unroll
        for (int q = 0; q < 4; q++) {
            int f = tid + q * 256;
            int row = f >> 3, kq = f & 7;
            int gr = brow + row;
            float4 v = make_float4(0.f, 0.f, 0.f, 0.f);
            if (gr < N) v = *(const float4*)&A[(size_t)gr * 128 + k0 + kq * 4];
            As[kq * 4 + 0][row] = v.x;
            As[kq * 4 + 1][row] = v.y;
            As[kq * 4 + 2][row] = v.z;
            As[kq * 4 + 3][row] = v.w;
        }
        constexpr int BF4 = BK * COUT / 4;
        #pragma unroll
        for (int f = tid; f < BF4; f += 256) {
            int row = f / (COUT / 4), cq = f % (COUT / 4);
            *(float4*)&Bs[row][cq * 4] = *(const float4*)&W[(size_t)(k0 + row) * COUT + cq * 4];
        }
        __syncthreads();
        #pragma unroll
        for (int kk = 0; kk < BK; kk++) {
            float a[8], b[TN];
            #pragma unroll
            for (int i = 0; i < 2; i++) {
                float4 av = *(const float4*)&As[kk][ty * 8 + i * 4];
                a[i * 4 + 0] = av.x; a[i * 4 + 1] = av.y;
                a[i * 4 + 2] = av.z; a[i * 4 + 3] = av.w;
            }
            #pragma unroll
            for (int j = 0; j < TN / 4; j++) {
                float4 bv = *(const float4*)&Bs[kk][tx * TN + j * 4];
                b[j * 4 + 0] = bv.x; b[j * 4 + 1] = bv.y;
                b[j * 4 + 2] = bv.z; b[j * 4 + 3] = bv.w;
            }
            #pragma unroll
            for (int i = 0; i < 8; i++)
                #pragma unroll
                for (int j = 0; j < TN; j++)
                    acc[i][j] = fmaf(a[i], b[j], acc[i][j]);
        }
        __syncthreads();
    }
    #pragma unroll
    for (int i = 0; i < 8; i++) {
        int r = brow + ty * 8 + i;
        if (r < N) {
            #pragma unroll
            for (int j = 0; j < TN / 4; j++)
                *(float4*)&out[(size_t)r * COUT + tx * TN + j * 4] =
                    make_float4(acc[i][j * 4], acc[i][j * 4 + 1], acc[i][j * 4 + 2], acc[i][j * 4 + 3]);
        }
    }
}

// ---------------- BN statistics: column sum / sumsq over act[N, COUT] ----------------
// blockDim = 256; thread handles channel (t % COUT), rows strided by 256/COUT.
template<int COUT>
__global__ __launch_bounds__(256) void k_bnstats(const float* __restrict__ act, int N) {
    constexpr int REP = 256 / COUT;
    __shared__ float s_s[256], s_q[256];
    int t = threadIdx.x;
    int c = t & (COUT - 1);
    int rep = t >> (COUT == 128 ? 7 : 6);
    int chunk = (N + gridDim.x - 1) / gridDim.x;
    int lo = blockIdx.x * chunk;
    int hi = min(lo + chunk, N);
    float s = 0.f, q = 0.f;
    for (int r = lo + rep; r < hi; r += REP) {
        float v = act[(size_t)r * COUT + c];
        s += v;
        q = fmaf(v, v, q);
    }
    s_s[t] = s; s_q[t] = q;
    __syncthreads();
    if (t < COUT) {
        #pragma unroll
        for (int w = 1; w < REP; w++) { s += s_s[t + w * COUT]; q += s_q[t + w * COUT]; }
        atomicAdd(&g_bnsum[t], s);
        atomicAdd(&g_bnsq[t],  q);
    }
}

// ---------------- BN params: scale/shift from sums, re-zero sums ----------------
template<int COUT>
__global__ void k_bnparam(const float* __restrict__ gam, const float* __restrict__ bet,
                          float invN) {
    int c = threadIdx.x;
    float m = g_bnsum[c] * invN;
    float v = g_bnsq[c] * invN - m * m;
    float inv = rsqrtf(v + 1e-5f);
    float sc = gam[c] * inv;
    g_scale[c] = sc;
    g_shift[c] = bet[c] - m * sc;
    g_bnsum[c] = 0.f;
    g_bnsq[c]  = 0.f;
}

// ---------------- final BN+ReLU writing d_out (LOUT channels) ----------------
__global__ void k_bnfinal(const float* __restrict__ act, float* __restrict__ out, int total) {
    int idx = blockIdx.x * blockDim.x + threadIdx.x;
    if (idx >= total) return;
    int c = idx & (LOUT - 1);
    out[idx] = fmaxf(fmaf(act[idx], g_scale[c], g_shift[c]), 0.f);
}

// ---------------- launch ----------------
extern "C" void kernel_launch(void* const* d_in, const int* in_sizes, int n_in,
                              void* d_out, int out_size) {
    const float* x   = (const float*)d_in[0];
    const void*  ei  = d_in[1];
    const float* ew  = (const float*)d_in[2];
    const float* W0  = (const float*)d_in[3];
    const float* ga0 = (const float*)d_in[5];
    const float* be0 = (const float*)d_in[6];
    const float* W1  = (const float*)d_in[7];
    const float* ga1 = (const float*)d_in[9];
    const float* be1 = (const float*)d_in[10];
    const float* Wf  = (const float*)d_in[11];
    const float* gaf = (const float*)d_in[13];
    const float* bef = (const float*)d_in[14];
    // biases d_in[4]/[8]/[12] are mathematically dead: BN's mean subtraction
    // cancels any per-channel constant added uniformly across rows.

    int N = in_sizes[0] / CH;
    int E = in_sizes[2];
    float invN = 1.0f / (float)N;

    // device addresses (never pass a __device__ symbol directly from host)
    float *agg_ptr = nullptr, *act_ptr = nullptr;
    cudaGetSymbolAddress((void**)&agg_ptr, g_agg);
    cudaGetSymbolAddress((void**)&act_ptr, g_act);

    int nb_e = (E + 255) / 256;
    int gemm_blocks = (N + 127) / 128;
    int agg_blocks  = (N * 32 + 255) / 256;

    // preprocessing
    k_deg<<<nb_e, 256>>>(ei, ew, E);
    k_scan_dis<<<1, 1024>>>(N);
    k_fill<<<nb_e, 256>>>(ei, ew, E);

    // layer 0
    k_agg<false><<<agg_blocks, 256>>>(x, agg_ptr, N);           // PROFILED SLOT
    k_gemm<CH><<<gemm_blocks, 256>>>(agg_ptr, W0, act_ptr, N);
    k_bnstats<CH><<<296, 256>>>(act_ptr, N);
    k_bnparam<CH><<<1, CH>>>(ga0, be0, invN);

    // layer 1 (BN+ReLU of layer 0 fused into agg loads)
    k_agg<true><<<agg_blocks, 256>>>(act_ptr, agg_ptr, N);
    k_gemm<CH><<<gemm_blocks, 256>>>(agg_ptr, W1, act_ptr, N);
    k_bnstats<CH><<<296, 256>>>(act_ptr, N);
    k_bnparam<CH><<<1, CH>>>(ga1, be1, invN);

    // layer 2
    k_agg<true><<<agg_blocks, 256>>>(act_ptr, agg_ptr, N);
    k_gemm<LOUT><<<gemm_blocks, 256>>>(agg_ptr, Wf, act_ptr, N);
    k_bnstats<LOUT><<<296, 256>>>(act_ptr, N);
    k_bnparam<LOUT><<<1, LOUT>>>(gaf, bef, invN);
    k_bnfinal<<<(N * LOUT + 255) / 256, 256>>>(act_ptr, (float*)d_out, N * LOUT);
}

// round 9
// speedup vs baseline: 1.2760x; 1.2760x over previous
#include <cuda_runtime.h>
#include <math.h>

// ---------------- problem constants ----------------
#define NMAX 50000
#define EMAX 800000
#define CH   128
#define LOUT 64

// ---------------- device scratch ----------------
struct alignas(8) Edge { int s; float nm; };
__device__ float g_deg[NMAX];        // zeroed each call by k_dis
__device__ float g_dis[NMAX];
__device__ float g_selfnorm[NMAX];
__device__ int   g_count[NMAX];      // zeroed each call by k_scan
__device__ int   g_rowstart[NMAX + 1];
__device__ int   g_cursor[NMAX];
__device__ Edge  g_csr[EMAX];
__device__ float g_act[(size_t)NMAX * CH];   // GEMM output (pre-agg)
__device__ float g_agg[(size_t)NMAX * CH];   // agg output h (pre-BN)
__device__ float g_bnsum[CH];        // zeroed after use (bnparam); zero-init at load
__device__ float g_bnsq[CH];
__device__ float g_scale[CH];
__device__ float g_shift[CH];

// ---------------- helpers ----------------
__device__ __forceinline__ bool idx_is64(const void* ei) {
    const int* w = (const int*)ei;
    return ((w[1] | w[3] | w[5] | w[7] | w[9]) == 0);
}
__device__ __forceinline__ int fetch_idx(const void* p, long long i, bool is64) {
    if (is64) return (int)((const long long*)p)[i];
    return ((const int*)p)[i];
}

// ---------------- degree + count accumulation ----------------
__global__ void k_deg(const void* ei, const float* __restrict__ ew, int E) {
    int e = blockIdx.x * blockDim.x + threadIdx.x;
    if (e >= E) return;
    bool is64 = idx_is64(ei);
    int d = fetch_idx(ei, (long long)E + e, is64);
    atomicAdd(&g_deg[d], ew[e]);
    atomicAdd(&g_count[d], 1);
}

// single block: exclusive scan of count -> rowstart/cursor; re-zero count.
__global__ void k_scan(int N) {
    __shared__ int ssum[1024];
    int t = threadIdx.x;
    int chunk = (N + 1023) / 1024;
    int lo = t * chunk;
    int hi = min(lo + chunk, N);
    int s = 0;
    for (int i = lo; i < hi; i++) s += g_count[i];
    ssum[t] = s;
    __syncthreads();
    for (int off = 1; off < 1024; off <<= 1) {
        int v = (t >= off) ? ssum[t - off] : 0;
        __syncthreads();
        ssum[t] += v;
        __syncthreads();
    }
    int base = (t == 0) ? 0 : ssum[t - 1];
    for (int i = lo; i < hi; i++) {
        g_rowstart[i] = base;
        g_cursor[i]   = base;
        base += g_count[i];
        g_count[i] = 0;
    }
    if (t == 1023) g_rowstart[N] = ssum[1023];
}

// parallel: dis/selfnorm from deg+1 (self loop); re-zero deg.
__global__ void k_dis(int N) {
    int i = blockIdx.x * blockDim.x + threadIdx.x;
    if (i >= N) return;
    float d = rsqrtf(g_deg[i] + 1.0f);
    g_dis[i] = d;
    g_selfnorm[i] = d * d;
    g_deg[i] = 0.f;
}

__global__ void k_fill(const void* ei, const float* __restrict__ ew, int E) {
    int e = blockIdx.x * blockDim.x + threadIdx.x;
    if (e >= E) return;
    bool is64 = idx_is64(ei);
    int s = fetch_idx(ei, e, is64);
    int d = fetch_idx(ei, (long long)E + e, is64);
    float nm = g_dis[s] * ew[e] * g_dis[d];
    int pos = atomicAdd(&g_cursor[d], 1);
    Edge ed; ed.s = s; ed.nm = nm;
    g_csr[pos] = ed;
}

// ---------------- SGEMM: out = f(A)[N,128] @ W[128,COUT], f = BN?scale/shift+relu ----
// R3-measured configuration (53.7us for COUT=128). Bias dead (cancels in BN).
template<int COUT, bool BN>
__global__ __launch_bounds__(256) void k_gemm(const float* __restrict__ A,
                                              const float* __restrict__ W,
                                              float* __restrict__ out, int N) {
    constexpr int BM = 128, BK = 32, TN = COUT / 16;
    __shared__ float As[BK][BM + 4];
    __shared__ float Bs[BK][COUT];
    __shared__ float s_scale[128];
    __shared__ float s_shift[128];
    int tid = threadIdx.x;
    int brow = blockIdx.x * BM;
    int ty = tid >> 4, tx = tid & 15;

    if (BN) {
        if (tid < 128) { s_scale[tid] = g_scale[tid]; s_shift[tid] = g_shift[tid]; }
        __syncthreads();
    }

    float acc[8][TN];
    #pragma unroll
    for (int i = 0; i < 8; i++)
        #pragma unroll
        for (int j = 0; j < TN; j++) acc[i][j] = 0.f;

    for (int k0 = 0; k0 < 128; k0 += BK) {
        #pragma unroll
        for (int q = 0; q < 4; q++) {
            int f = tid + q * 256;
            int row = f >> 3, kq = f & 7;
            int gr = brow + row;
            float4 v = make_float4(0.f, 0.f, 0.f, 0.f);
            if (gr < N) v = *(const float4*)&A[(size_t)gr * 128 + k0 + kq * 4];
            if (BN) {
                int c = k0 + kq * 4;
                v.x = fmaxf(fmaf(v.x, s_scale[c + 0], s_shift[c + 0]), 0.f);
                v.y = fmaxf(fmaf(v.y, s_scale[c + 1], s_shift[c + 1]), 0.f);
                v.z = fmaxf(fmaf(v.z, s_scale[c + 2], s_shift[c + 2]), 0.f);
                v.w = fmaxf(fmaf(v.w, s_scale[c + 3], s_shift[c + 3]), 0.f);
            }
            As[kq * 4 + 0][row] = v.x;
            As[kq * 4 + 1][row] = v.y;
            As[kq * 4 + 2][row] = v.z;
            As[kq * 4 + 3][row] = v.w;
        }
        constexpr int BF4 = BK * COUT / 4;
        #pragma unroll
        for (int f = tid; f < BF4; f += 256) {
            int row = f / (COUT / 4), cq = f % (COUT / 4);
            *(float4*)&Bs[row][cq * 4] = *(const float4*)&W[(size_t)(k0 + row) * COUT + cq * 4];
        }
        __syncthreads();
        #pragma unroll
        for (int kk = 0; kk < BK; kk++) {
            float a[8], b[TN];
            #pragma unroll
            for (int i = 0; i < 2; i++) {
                float4 av = *(const float4*)&As[kk][ty * 8 + i * 4];
                a[i * 4 + 0] = av.x; a[i * 4 + 1] = av.y;
                a[i * 4 + 2] = av.z; a[i * 4 + 3] = av.w;
            }
            #pragma unroll
            for (int j = 0; j < TN / 4; j++) {
                float4 bv = *(const float4*)&Bs[kk][tx * TN + j * 4];
                b[j * 4 + 0] = bv.x; b[j * 4 + 1] = bv.y;
                b[j * 4 + 2] = bv.z; b[j * 4 + 3] = bv.w;
            }
            #pragma unroll
            for (int i = 0; i < 8; i++)
                #pragma unroll
                for (int j = 0; j < TN; j++)
                    acc[i][j] = fmaf(a[i], b[j], acc[i][j]);
        }
        __syncthreads();
    }
    #pragma unroll
    for (int i = 0; i < 8; i++) {
        int r = brow + ty * 8 + i;
        if (r < N) {
            #pragma unroll
            for (int j = 0; j < TN / 4; j++)
                *(float4*)&out[(size_t)r * COUT + tx * TN + j * 4] =
                    make_float4(acc[i][j * 4], acc[i][j * 4 + 1], acc[i][j * 4 + 2], acc[i][j * 4 + 3]);
        }
    }
}

// ---------------- aggregation: out = S * act  (plain, barrier-free, warp/node) ----
template<int W>
__global__ void k_agg(const float* __restrict__ act, float* __restrict__ out, int N) {
    constexpr int V = W / 32;
    int gw   = (blockIdx.x * blockDim.x + threadIdx.x) >> 5;
    int lane = threadIdx.x & 31;
    if (gw >= N) return;

    float sn = g_selfnorm[gw];
    float acc[V];
    if constexpr (V == 4) {
        float4 tv = *(const float4*)&act[(size_t)gw * W + lane * 4];
        acc[0] = sn * tv.x; acc[1] = sn * tv.y; acc[2] = sn * tv.z; acc[3] = sn * tv.w;
    } else {
        float2 tv = *(const float2*)&act[(size_t)gw * W + lane * 2];
        acc[0] = sn * tv.x; acc[1] = sn * tv.y;
    }
    int r0 = g_rowstart[gw], r1 = g_rowstart[gw + 1];
    #pragma unroll 4
    for (int e = r0; e < r1; e++) {
        Edge ed = g_csr[e];
        float nm = ed.nm;
        if constexpr (V == 4) {
            float4 v = *(const float4*)&act[(size_t)ed.s * W + lane * 4];
            acc[0] = fmaf(nm, v.x, acc[0]); acc[1] = fmaf(nm, v.y, acc[1]);
            acc[2] = fmaf(nm, v.z, acc[2]); acc[3] = fmaf(nm, v.w, acc[3]);
        } else {
            float2 v = *(const float2*)&act[(size_t)ed.s * W + lane * 2];
            acc[0] = fmaf(nm, v.x, acc[0]); acc[1] = fmaf(nm, v.y, acc[1]);
        }
    }
    if constexpr (V == 4) {
        *(float4*)&out[(size_t)gw * W + lane * 4] = make_float4(acc[0], acc[1], acc[2], acc[3]);
    } else {
        *(float2*)&out[(size_t)gw * W + lane * 2] = make_float2(acc[0], acc[1]);
    }
}

// ---------------- BN statistics: column sum / sumsq over h[N, COUT] ----------------
template<int COUT>
__global__ __launch_bounds__(256) void k_bnstats(const float* __restrict__ h, int N) {
    constexpr int REP = 256 / COUT;
    __shared__ float s_s[256], s_q[256];
    int t = threadIdx.x;
    int c = t & (COUT - 1);
    int rep = t / COUT;
    int chunk = (N + gridDim.x - 1) / gridDim.x;
    int lo = blockIdx.x * chunk;
    int hi = min(lo + chunk, N);
    float s = 0.f, q = 0.f;
    for (int r = lo + rep; r < hi; r += REP) {
        float v = h[(size_t)r * COUT + c];
        s += v;
        q = fmaf(v, v, q);
    }
    s_s[t] = s; s_q[t] = q;
    __syncthreads();
    if (t < COUT) {
        #pragma unroll
        for (int w = 1; w < REP; w++) { s += s_s[t + w * COUT]; q += s_q[t + w * COUT]; }
        atomicAdd(&g_bnsum[t], s);
        atomicAdd(&g_bnsq[t],  q);
    }
}

// ---------------- BN params: scale/shift from sums, re-zero sums ----------------
template<int COUT>
__global__ void k_bnparam(const float* __restrict__ gam, const float* __restrict__ bet,
                          float invN) {
    int c = threadIdx.x;
    float m = g_bnsum[c] * invN;
    float v = g_bnsq[c] * invN - m * m;
    float inv = rsqrtf(v + 1e-5f);
    float sc = gam[c] * inv;
    g_scale[c] = sc;
    g_shift[c] = bet[c] - m * sc;
    g_bnsum[c] = 0.f;
    g_bnsq[c]  = 0.f;
}

// ---------------- final BN+ReLU writing d_out (LOUT channels) ----------------
__global__ void k_bnfinal(const float* __restrict__ h, float* __restrict__ out, int total) {
    int idx = blockIdx.x * blockDim.x + threadIdx.x;
    if (idx >= total) return;
    int c = idx & (LOUT - 1);
    out[idx] = fmaxf(fmaf(h[idx], g_scale[c], g_shift[c]), 0.f);
}

// ---------------- launch ----------------
extern "C" void kernel_launch(void* const* d_in, const int* in_sizes, int n_in,
                              void* d_out, int out_size) {
    const float* x   = (const float*)d_in[0];
    const void*  ei  = d_in[1];
    const float* ew  = (const float*)d_in[2];
    const float* W0  = (const float*)d_in[3];
    const float* ga0 = (const float*)d_in[5];
    const float* be0 = (const float*)d_in[6];
    const float* W1  = (const float*)d_in[7];
    const float* ga1 = (const float*)d_in[9];
    const float* be1 = (const float*)d_in[10];
    const float* Wf  = (const float*)d_in[11];
    const float* gaf = (const float*)d_in[13];
    const float* bef = (const float*)d_in[14];
    // biases d_in[4]/[8]/[12] are dead: BN mean-subtraction cancels them exactly.

    int N = in_sizes[0] / CH;
    int E = in_sizes[2];
    float invN = 1.0f / (float)N;

    float *act_ptr = nullptr, *agg_ptr = nullptr;
    cudaGetSymbolAddress((void**)&act_ptr, g_act);
    cudaGetSymbolAddress((void**)&agg_ptr, g_agg);

    int nb_e = (E + 255) / 256;
    int nb_n = (N + 255) / 256;
    int gemm_blocks = (N + 127) / 128;
    int agg_blocks   = (N * 32 + 255) / 256;

    // preprocessing; gemm0 (no deps) takes the profiled 4th slot
    k_deg<<<nb_e, 256>>>(ei, ew, E);
    k_scan<<<1, 1024>>>(N);
    k_dis<<<nb_n, 256>>>(N);
    k_gemm<CH, false><<<gemm_blocks, 256>>>(x, W0, act_ptr, N);   // PROFILED SLOT (4th)
    k_fill<<<nb_e, 256>>>(ei, ew, E);

    // layer 0: h0 = S * act0; stats(h0)
    k_agg<CH><<<agg_blocks, 256>>>(act_ptr, agg_ptr, N);
    k_bnstats<CH><<<296, 256>>>(agg_ptr, N);
    k_bnparam<CH><<<1, CH>>>(ga0, be0, invN);

    // layer 1: act1 = f(h0) @ W1 (BN fused in A-load); h1 = S * act1
    k_gemm<CH, true><<<gemm_blocks, 256>>>(agg_ptr, W1, act_ptr, N);
    k_agg<CH><<<agg_blocks, 256>>>(act_ptr, agg_ptr, N);
    k_bnstats<CH><<<296, 256>>>(agg_ptr, N);
    k_bnparam<CH><<<1, CH>>>(ga1, be1, invN);

    // layer 2: act2 = f(h1) @ Wf [N,64]; h2 = S * act2 (64-wide agg = half traffic)
    k_gemm<LOUT, true><<<gemm_blocks, 256>>>(agg_ptr, Wf, act_ptr, N);
    k_agg<LOUT><<<agg_blocks, 256>>>(act_ptr, agg_ptr, N);
    k_bnstats<LOUT><<<296, 256>>>(agg_ptr, N);
    k_bnparam<LOUT><<<1, LOUT>>>(gaf, bef, invN);
    k_bnfinal<<<(N * LOUT + 255) / 256, 256>>>(agg_ptr, (float*)d_out, N * LOUT);
}

// round 10
// speedup vs baseline: 1.7275x; 1.3539x over previous
#include <cuda_runtime.h>
#include <math.h>

// ---------------- problem constants ----------------
#define NMAX 50000
#define EMAX 800000
#define CH   128
#define LOUT 64
#define SCHUNK 1024   // counts per scan block

// ---------------- device scratch ----------------
struct alignas(8) Edge { int s; float nm; };
__device__ float g_deg[NMAX];        // zeroed each call by k_scan3
__device__ float g_dis[NMAX];
__device__ float g_selfnorm[NMAX];
__device__ int   g_count[NMAX];      // zeroed each call by k_scan3
__device__ int   g_rowstart[NMAX + 1];
__device__ int   g_cursor[NMAX];
__device__ int   g_partial[64];      // block partial sums -> exclusive offsets
__device__ Edge  g_csr[EMAX];
__device__ float g_act[(size_t)NMAX * CH];   // GEMM output (pre-agg)
__device__ float g_agg[(size_t)NMAX * CH];   // agg output h (pre-BN)
__device__ float g_bnsum[CH];        // zeroed by bnstats last block
__device__ float g_bnsq[CH];
__device__ float g_scale[CH];
__device__ float g_shift[CH];
__device__ int   g_ticket;           // bnstats last-block ticket (reset each use)

// ---------------- helpers ----------------
__device__ __forceinline__ bool idx_is64(const void* ei) {
    const int* w = (const int*)ei;
    return ((w[1] | w[3] | w[5] | w[7] | w[9]) == 0);
}
__device__ __forceinline__ int fetch_idx(const void* p, long long i, bool is64) {
    if (is64) return (int)((const long long*)p)[i];
    return ((const int*)p)[i];
}

// ---------------- degree + count accumulation ----------------
__global__ void k_deg(const void* ei, const float* __restrict__ ew, int E) {
    int e = blockIdx.x * blockDim.x + threadIdx.x;
    if (e >= E) return;
    bool is64 = idx_is64(ei);
    int d = fetch_idx(ei, (long long)E + e, is64);
    atomicAdd(&g_deg[d], ew[e]);
    atomicAdd(&g_count[d], 1);
}

// ---------------- parallel scan, phase 1: per-block sums (coalesced) ----------------
__global__ __launch_bounds__(256) void k_scan1(int N) {
    int base = blockIdx.x * SCHUNK + threadIdx.x * 4;
    int s = 0;
    #pragma unroll
    for (int k = 0; k < 4; k++) { int i = base + k; if (i < N) s += g_count[i]; }
    #pragma unroll
    for (int o = 16; o > 0; o >>= 1) s += __shfl_down_sync(0xffffffffu, s, o);
    __shared__ int ws[8];
    if ((threadIdx.x & 31) == 0) ws[threadIdx.x >> 5] = s;
    __syncthreads();
    if (threadIdx.x < 8) {
        int v = ws[threadIdx.x];
        #pragma unroll
        for (int o = 4; o > 0; o >>= 1) v += __shfl_down_sync(0xffu, v, o, 8);
        if (threadIdx.x == 0) g_partial[blockIdx.x] = v;
    }
}

// phase 2: single small block scans <=64 partials -> exclusive offsets in place
__global__ void k_scan2(int nb) {
    __shared__ int sh[64];
    int t = threadIdx.x;                 // blockDim = 64
    int v = (t < nb) ? g_partial[t] : 0;
    sh[t] = v;
    __syncthreads();
    #pragma unroll
    for (int o = 1; o < 64; o <<= 1) {
        int u = (t >= o) ? sh[t - o] : 0;
        __syncthreads();
        sh[t] += u;
        __syncthreads();
    }
    g_partial[t] = sh[t] - v;            // exclusive
}

// phase 3: block-local exclusive scan + offsets; write rowstart/cursor; zero count;
// fused k_dis: dis/selfnorm from deg+1; zero deg.
__global__ __launch_bounds__(256) void k_scan3(int N, int E) {
    int t = threadIdx.x, lane = t & 31, w = t >> 5;
    int base = blockIdx.x * SCHUNK + t * 4;
    int c[4]; int s = 0;
    #pragma unroll
    for (int k = 0; k < 4; k++) {
        int i = base + k;
        c[k] = (i < N) ? g_count[i] : 0;
        s += c[k];
    }
    // warp inclusive scan of thread totals
    int incl = s;
    #pragma unroll
    for (int o = 1; o < 32; o <<= 1) {
        int u = __shfl_up_sync(0xffffffffu, incl, o);
        if (lane >= o) incl += u;
    }
    int wexcl = incl - s;
    __shared__ int wtot[8], woff[8];
    if (lane == 31) wtot[w] = incl;
    __syncthreads();
    if (t < 8) {
        int v = wtot[t], iv = v;
        #pragma unroll
        for (int o = 1; o < 8; o <<= 1) {
            int u = __shfl_up_sync(0xffu, iv, o, 8);
            if (t >= o) iv += u;
        }
        woff[t] = iv - v;
    }
    __syncthreads();
    int run = g_partial[blockIdx.x] + woff[w] + wexcl;
    #pragma unroll
    for (int k = 0; k < 4; k++) {
        int i = base + k;
        if (i < N) {
            g_rowstart[i] = run;
            g_cursor[i]   = run;
            run += c[k];
            g_count[i] = 0;
            float d = rsqrtf(g_deg[i] + 1.0f);   // +1 self-loop
            g_dis[i] = d;
            g_selfnorm[i] = d * d;
            g_deg[i] = 0.f;
        }
    }
    if (blockIdx.x == 0 && t == 0) g_rowstart[N] = E;
}

__global__ void k_fill(const void* ei, const float* __restrict__ ew, int E) {
    int e = blockIdx.x * blockDim.x + threadIdx.x;
    if (e >= E) return;
    bool is64 = idx_is64(ei);
    int s = fetch_idx(ei, e, is64);
    int d = fetch_idx(ei, (long long)E + e, is64);
    float nm = g_dis[s] * ew[e] * g_dis[d];
    int pos = atomicAdd(&g_cursor[d], 1);
    Edge ed; ed.s = s; ed.nm = nm;
    g_csr[pos] = ed;
}

// ---------------- SGEMM: out = f(A)[N,128] @ W[128,COUT], f = BN?scale/shift+relu ----
template<int COUT, bool BN>
__global__ __launch_bounds__(256) void k_gemm(const float* __restrict__ A,
                                              const float* __restrict__ W,
                                              float* __restrict__ out, int N) {
    constexpr int BM = 128, BK = 32, TN = COUT / 16;
    __shared__ float As[BK][BM + 4];
    __shared__ float Bs[BK][COUT];
    __shared__ float s_scale[128];
    __shared__ float s_shift[128];
    int tid = threadIdx.x;
    int brow = blockIdx.x * BM;
    int ty = tid >> 4, tx = tid & 15;

    if (BN) {
        if (tid < 128) { s_scale[tid] = g_scale[tid]; s_shift[tid] = g_shift[tid]; }
        __syncthreads();
    }

    float acc[8][TN];
    #pragma unroll
    for (int i = 0; i < 8; i++)
        #pragma unroll
        for (int j = 0; j < TN; j++) acc[i][j] = 0.f;

    for (int k0 = 0; k0 < 128; k0 += BK) {
        #pragma unroll
        for (int q = 0; q < 4; q++) {
            int f = tid + q * 256;
            int row = f >> 3, kq = f & 7;
            int gr = brow + row;
            float4 v = make_float4(0.f, 0.f, 0.f, 0.f);
            if (gr < N) v = *(const float4*)&A[(size_t)gr * 128 + k0 + kq * 4];
            if (BN) {
                int c = k0 + kq * 4;
                v.x = fmaxf(fmaf(v.x, s_scale[c + 0], s_shift[c + 0]), 0.f);
                v.y = fmaxf(fmaf(v.y, s_scale[c + 1], s_shift[c + 1]), 0.f);
                v.z = fmaxf(fmaf(v.z, s_scale[c + 2], s_shift[c + 2]), 0.f);
                v.w = fmaxf(fmaf(v.w, s_scale[c + 3], s_shift[c + 3]), 0.f);
            }
            As[kq * 4 + 0][row] = v.x;
            As[kq * 4 + 1][row] = v.y;
            As[kq * 4 + 2][row] = v.z;
            As[kq * 4 + 3][row] = v.w;
        }
        constexpr int BF4 = BK * COUT / 4;
        #pragma unroll
        for (int f = tid; f < BF4; f += 256) {
            int row = f / (COUT / 4), cq = f % (COUT / 4);
            *(float4*)&Bs[row][cq * 4] = *(const float4*)&W[(size_t)(k0 + row) * COUT + cq * 4];
        }
        __syncthreads();
        #pragma unroll
        for (int kk = 0; kk < BK; kk++) {
            float a[8], b[TN];
            #pragma unroll
            for (int i = 0; i < 2; i++) {
                float4 av = *(const float4*)&As[kk][ty * 8 + i * 4];
                a[i * 4 + 0] = av.x; a[i * 4 + 1] = av.y;
                a[i * 4 + 2] = av.z; a[i * 4 + 3] = av.w;
            }
            #pragma unroll
            for (int j = 0; j < TN / 4; j++) {
                float4 bv = *(const float4*)&Bs[kk][tx * TN + j * 4];
                b[j * 4 + 0] = bv.x; b[j * 4 + 1] = bv.y;
                b[j * 4 + 2] = bv.z; b[j * 4 + 3] = bv.w;
            }
            #pragma unroll
            for (int i = 0; i < 8; i++)
                #pragma unroll
                for (int j = 0; j < TN; j++)
                    acc[i][j] = fmaf(a[i], b[j], acc[i][j]);
        }
        __syncthreads();
    }
    #pragma unroll
    for (int i = 0; i < 8; i++) {
        int r = brow + ty * 8 + i;
        if (r < N) {
            #pragma unroll
            for (int j = 0; j < TN / 4; j++)
                *(float4*)&out[(size_t)r * COUT + tx * TN + j * 4] =
                    make_float4(acc[i][j * 4], acc[i][j * 4 + 1], acc[i][j * 4 + 2], acc[i][j * 4 + 3]);
        }
    }
}

// ---------------- aggregation: out = S * act  (plain, barrier-free, warp/node) ----
template<int W>
__global__ void k_agg(const float* __restrict__ act, float* __restrict__ out, int N) {
    constexpr int V = W / 32;
    int gw   = (blockIdx.x * blockDim.x + threadIdx.x) >> 5;
    int lane = threadIdx.x & 31;
    if (gw >= N) return;

    float sn = g_selfnorm[gw];
    float acc[V];
    if constexpr (V == 4) {
        float4 tv = *(const float4*)&act[(size_t)gw * W + lane * 4];
        acc[0] = sn * tv.x; acc[1] = sn * tv.y; acc[2] = sn * tv.z; acc[3] = sn * tv.w;
    } else {
        float2 tv = *(const float2*)&act[(size_t)gw * W + lane * 2];
        acc[0] = sn * tv.x; acc[1] = sn * tv.y;
    }
    int r0 = g_rowstart[gw], r1 = g_rowstart[gw + 1];
    #pragma unroll 4
    for (int e = r0; e < r1; e++) {
        Edge ed = g_csr[e];
        float nm = ed.nm;
        if constexpr (V == 4) {
            float4 v = *(const float4*)&act[(size_t)ed.s * W + lane * 4];
            acc[0] = fmaf(nm, v.x, acc[0]); acc[1] = fmaf(nm, v.y, acc[1]);
            acc[2] = fmaf(nm, v.z, acc[2]); acc[3] = fmaf(nm, v.w, acc[3]);
        } else {
            float2 v = *(const float2*)&act[(size_t)ed.s * W + lane * 2];
            acc[0] = fmaf(nm, v.x, acc[0]); acc[1] = fmaf(nm, v.y, acc[1]);
        }
    }
    if constexpr (V == 4) {
        *(float4*)&out[(size_t)gw * W + lane * 4] = make_float4(acc[0], acc[1], acc[2], acc[3]);
    } else {
        *(float2*)&out[(size_t)gw * W + lane * 2] = make_float2(acc[0], acc[1]);
    }
}

// ---------------- BN stats + fused param computation (last-block pattern) ----------
template<int COUT>
__global__ __launch_bounds__(256) void k_bnstats(const float* __restrict__ h,
                                                 const float* __restrict__ gam,
                                                 const float* __restrict__ bet,
                                                 int N, float invN) {
    constexpr int REP = 256 / COUT;
    __shared__ float s_s[256], s_q[256];
    __shared__ bool is_last;
    int t = threadIdx.x;
    int c = t & (COUT - 1);
    int rep = t / COUT;
    int chunk = (N + gridDim.x - 1) / gridDim.x;
    int lo = blockIdx.x * chunk;
    int hi = min(lo + chunk, N);
    float s = 0.f, q = 0.f;
    for (int r = lo + rep; r < hi; r += REP) {
        float v = h[(size_t)r * COUT + c];
        s += v;
        q = fmaf(v, v, q);
    }
    s_s[t] = s; s_q[t] = q;
    __syncthreads();
    if (t < COUT) {
        #pragma unroll
        for (int w = 1; w < REP; w++) { s += s_s[t + w * COUT]; q += s_q[t + w * COUT]; }
        atomicAdd(&g_bnsum[t], s);
        atomicAdd(&g_bnsq[t],  q);
    }
    // last block computes scale/shift and resets accumulators
    __threadfence();
    if (t == 0) {
        int v = atomicAdd(&g_ticket, 1);
        is_last = (v == (int)gridDim.x - 1);
    }
    __syncthreads();
    if (is_last) {
        if (t == 0) g_ticket = 0;
        if (t < COUT) {
            float ms = atomicAdd(&g_bnsum[t], 0.f);   // L2-coherent read
            float mq = atomicAdd(&g_bnsq[t], 0.f);
            float m  = ms * invN;
            float va = mq * invN - m * m;
            float inv = rsqrtf(va + 1e-5f);
            float sc = gam[t] * inv;
            g_scale[t] = sc;
            g_shift[t] = bet[t] - m * sc;
            g_bnsum[t] = 0.f;
            g_bnsq[t]  = 0.f;
        }
    }
}

// ---------------- final BN+ReLU writing d_out (LOUT channels) ----------------
__global__ void k_bnfinal(const float* __restrict__ h, float* __restrict__ out, int total) {
    int idx = blockIdx.x * blockDim.x + threadIdx.x;
    if (idx >= total) return;
    int c = idx & (LOUT - 1);
    out[idx] = fmaxf(fmaf(h[idx], g_scale[c], g_shift[c]), 0.f);
}

// ---------------- launch ----------------
extern "C" void kernel_launch(void* const* d_in, const int* in_sizes, int n_in,
                              void* d_out, int out_size) {
    const float* x   = (const float*)d_in[0];
    const void*  ei  = d_in[1];
    const float* ew  = (const float*)d_in[2];
    const float* W0  = (const float*)d_in[3];
    const float* ga0 = (const float*)d_in[5];
    const float* be0 = (const float*)d_in[6];
    const float* W1  = (const float*)d_in[7];
    const float* ga1 = (const float*)d_in[9];
    const float* be1 = (const float*)d_in[10];
    const float* Wf  = (const float*)d_in[11];
    const float* gaf = (const float*)d_in[13];
    const float* bef = (const float*)d_in[14];
    // biases d_in[4]/[8]/[12] are dead: BN mean-subtraction cancels them exactly.

    int N = in_sizes[0] / CH;
    int E = in_sizes[2];
    float invN = 1.0f / (float)N;

    float *act_ptr = nullptr, *agg_ptr = nullptr;
    cudaGetSymbolAddress((void**)&act_ptr, g_act);
    cudaGetSymbolAddress((void**)&agg_ptr, g_agg);

    int nb_e = (E + 255) / 256;
    int nb_scan = (N + SCHUNK - 1) / SCHUNK;
    int gemm_blocks = (N + 127) / 128;
    int agg_blocks  = (N * 32 + 255) / 256;

    // preprocessing (fully parallel scan; scan3 = profiled 4th slot)
    k_deg<<<nb_e, 256>>>(ei, ew, E);
    k_scan1<<<nb_scan, 256>>>(N);
    k_scan2<<<1, 64>>>(nb_scan);
    k_scan3<<<nb_scan, 256>>>(N, E);             // PROFILED SLOT (4th)
    k_fill<<<nb_e, 256>>>(ei, ew, E);
    k_gemm<CH, false><<<gemm_blocks, 256>>>(x, W0, act_ptr, N);

    // layer 0
    k_agg<CH><<<agg_blocks, 256>>>(act_ptr, agg_ptr, N);
    k_bnstats<CH><<<296, 256>>>(agg_ptr, ga0, be0, N, invN);

    // layer 1
    k_gemm<CH, true><<<gemm_blocks, 256>>>(agg_ptr, W1, act_ptr, N);
    k_agg<CH><<<agg_blocks, 256>>>(act_ptr, agg_ptr, N);
    k_bnstats<CH><<<296, 256>>>(agg_ptr, ga1, be1, N, invN);

    // layer 2 (64-wide agg)
    k_gemm<LOUT, true><<<gemm_blocks, 256>>>(agg_ptr, Wf, act_ptr, N);
    k_agg<LOUT><<<agg_blocks, 256>>>(act_ptr, agg_ptr, N);
    k_bnstats<LOUT><<<296, 256>>>(agg_ptr, gaf, bef, N, invN);
    k_bnfinal<<<(N * LOUT + 255) / 256, 256>>>(agg_ptr, (float*)d_out, N * LOUT);
}

// round 11
// speedup vs baseline: 1.7590x; 1.0183x over previous
#include <cuda_runtime.h>
#include <math.h>

// ---------------- problem constants ----------------
#define NMAX 50000
#define EMAX 800000
#define CH   128
#define LOUT 64
#define SCHUNK 1024   // counts per scan block
#define BKC  16       // GEMM k-chunk

// ---------------- device scratch ----------------
struct alignas(8) Edge { int s; float nm; };
__device__ float g_deg[NMAX];        // zeroed each call by k_scan3
__device__ float g_dis[NMAX];
__device__ float g_selfnorm[NMAX];
__device__ int   g_count[NMAX];      // zeroed each call by k_scan3
__device__ int   g_rowstart[NMAX + 1];
__device__ int   g_cursor[NMAX];
__device__ int   g_partial[64];
__device__ Edge  g_csr[EMAX];
__device__ float g_act[(size_t)NMAX * CH];
__device__ float g_agg[(size_t)NMAX * CH];
__device__ float g_bnsum[CH];
__device__ float g_bnsq[CH];
__device__ float g_scale[CH];
__device__ float g_shift[CH];
__device__ int   g_ticket;

// ---------------- helpers ----------------
__device__ __forceinline__ bool idx_is64(const void* ei) {
    const int* w = (const int*)ei;
    return ((w[1] | w[3] | w[5] | w[7] | w[9]) == 0);
}
__device__ __forceinline__ int fetch_idx(const void* p, long long i, bool is64) {
    if (is64) return (int)((const long long*)p)[i];
    return ((const int*)p)[i];
}
__device__ __forceinline__ void cvt2tf32(float x, unsigned& hi, unsigned& lo) {
    asm("cvt.rna.tf32.f32 %0, %1;" : "=r"(hi) : "f"(x));
    float l = x - __uint_as_float(hi);
    asm("cvt.rna.tf32.f32 %0, %1;" : "=r"(lo) : "f"(l));
}
__device__ __forceinline__ void mma_tf32(float* c, const unsigned* a, unsigned b0, unsigned b1) {
    asm volatile("mma.sync.aligned.m16n8k8.row.col.f32.tf32.tf32.f32 "
        "{%0,%1,%2,%3}, {%4,%5,%6,%7}, {%8,%9}, {%0,%1,%2,%3};"
        : "+f"(c[0]), "+f"(c[1]), "+f"(c[2]), "+f"(c[3])
        : "r"(a[0]), "r"(a[1]), "r"(a[2]), "r"(a[3]), "r"(b0), "r"(b1));
}

// ---------------- degree + count accumulation ----------------
__global__ void k_deg(const void* ei, const float* __restrict__ ew, int E) {
    int e = blockIdx.x * blockDim.x + threadIdx.x;
    if (e >= E) return;
    bool is64 = idx_is64(ei);
    int d = fetch_idx(ei, (long long)E + e, is64);
    atomicAdd(&g_deg[d], ew[e]);
    atomicAdd(&g_count[d], 1);
}

// ---------------- parallel scan phases ----------------
__global__ __launch_bounds__(256) void k_scan1(int N) {
    int base = blockIdx.x * SCHUNK + threadIdx.x * 4;
    int s = 0;
    #pragma unroll
    for (int k = 0; k < 4; k++) { int i = base + k; if (i < N) s += g_count[i]; }
    #pragma unroll
    for (int o = 16; o > 0; o >>= 1) s += __shfl_down_sync(0xffffffffu, s, o);
    __shared__ int ws[8];
    if ((threadIdx.x & 31) == 0) ws[threadIdx.x >> 5] = s;
    __syncthreads();
    if (threadIdx.x < 8) {
        int v = ws[threadIdx.x];
        #pragma unroll
        for (int o = 4; o > 0; o >>= 1) v += __shfl_down_sync(0xffu, v, o, 8);
        if (threadIdx.x == 0) g_partial[blockIdx.x] = v;
    }
}

__global__ void k_scan2(int nb) {
    __shared__ int sh[64];
    int t = threadIdx.x;
    int v = (t < nb) ? g_partial[t] : 0;
    sh[t] = v;
    __syncthreads();
    #pragma unroll
    for (int o = 1; o < 64; o <<= 1) {
        int u = (t >= o) ? sh[t - o] : 0;
        __syncthreads();
        sh[t] += u;
        __syncthreads();
    }
    g_partial[t] = sh[t] - v;
}

__global__ __launch_bounds__(256) void k_scan3(int N, int E) {
    int t = threadIdx.x, lane = t & 31, w = t >> 5;
    int base = blockIdx.x * SCHUNK + t * 4;
    int c[4]; int s = 0;
    #pragma unroll
    for (int k = 0; k < 4; k++) {
        int i = base + k;
        c[k] = (i < N) ? g_count[i] : 0;
        s += c[k];
    }
    int incl = s;
    #pragma unroll
    for (int o = 1; o < 32; o <<= 1) {
        int u = __shfl_up_sync(0xffffffffu, incl, o);
        if (lane >= o) incl += u;
    }
    int wexcl = incl - s;
    __shared__ int wtot[8], woff[8];
    if (lane == 31) wtot[w] = incl;
    __syncthreads();
    if (t < 8) {
        int v = wtot[t], iv = v;
        #pragma unroll
        for (int o = 1; o < 8; o <<= 1) {
            int u = __shfl_up_sync(0xffu, iv, o, 8);
            if (t >= o) iv += u;
        }
        woff[t] = iv - v;
    }
    __syncthreads();
    int run = g_partial[blockIdx.x] + woff[w] + wexcl;
    #pragma unroll
    for (int k = 0; k < 4; k++) {
        int i = base + k;
        if (i < N) {
            g_rowstart[i] = run;
            g_cursor[i]   = run;
            run += c[k];
            g_count[i] = 0;
            float d = rsqrtf(g_deg[i] + 1.0f);
            g_dis[i] = d;
            g_selfnorm[i] = d * d;
            g_deg[i] = 0.f;
        }
    }
    if (blockIdx.x == 0 && t == 0) g_rowstart[N] = E;
}

__global__ void k_fill(const void* ei, const float* __restrict__ ew, int E) {
    int e = blockIdx.x * blockDim.x + threadIdx.x;
    if (e >= E) return;
    bool is64 = idx_is64(ei);
    int s = fetch_idx(ei, e, is64);
    int d = fetch_idx(ei, (long long)E + e, is64);
    float nm = g_dis[s] * ew[e] * g_dis[d];
    int pos = atomicAdd(&g_cursor[d], 1);
    Edge ed; ed.s = s; ed.nm = nm;
    g_csr[pos] = ed;
}

// ---------------- tf32 tensor GEMM: out = f(A)[N,128] @ W[128,COUT] ----------------
// 3-term precision split (hi*hi + hi*lo + lo*hi), rel err ~2^-22.
// 8 warps as 4(m) x 2(n); warp tile 32 x COUT/2; BK=16.
template<int COUT, bool BN>
__global__ __launch_bounds__(256) void k_gemm(const float* __restrict__ A,
                                              const float* __restrict__ W,
                                              float* __restrict__ out, int N) {
    constexpr int AS = 20;          // A smem row stride (u32), conflict-free frags
    constexpr int BS = COUT + 8;    // B smem k-row stride (u32), conflict-free frags
    constexpr int NT = COUT / 16;   // n8 tiles per warp
    __shared__ unsigned sAh[128 * AS], sAl[128 * AS];
    __shared__ unsigned sBh[BKC * BS], sBl[BKC * BS];
    __shared__ float s_scale[128], s_shift[128];

    int tid = threadIdx.x;
    int lane = tid & 31, w = tid >> 5;
    int wm = w & 3, wn = w >> 2;
    int brow = blockIdx.x * 128;
    int g = lane >> 2, t4 = lane & 3;

    if (BN) {
        if (tid < 128) { s_scale[tid] = g_scale[tid]; s_shift[tid] = g_shift[tid]; }
        __syncthreads();
    }

    float acc[2][NT][4];
    #pragma unroll
    for (int i = 0; i < 2; i++)
        #pragma unroll
        for (int j = 0; j < NT; j++)
            #pragma unroll
            for (int q = 0; q < 4; q++) acc[i][j][q] = 0.f;

    for (int k0 = 0; k0 < 128; k0 += BKC) {
        // A tile 128 x 16: 512 float4; thread handles 2
        #pragma unroll
        for (int q = 0; q < 2; q++) {
            int f = tid + q * 256;
            int row = f >> 2;
            int kc = (f & 3) * 4;
            int gr = brow + row;
            float4 v = make_float4(0.f, 0.f, 0.f, 0.f);
            if (gr < N) v = *(const float4*)&A[(size_t)gr * 128 + k0 + kc];
            if (BN) {
                int c = k0 + kc;
                v.x = fmaxf(fmaf(v.x, s_scale[c + 0], s_shift[c + 0]), 0.f);
                v.y = fmaxf(fmaf(v.y, s_scale[c + 1], s_shift[c + 1]), 0.f);
                v.z = fmaxf(fmaf(v.z, s_scale[c + 2], s_shift[c + 2]), 0.f);
                v.w = fmaxf(fmaf(v.w, s_scale[c + 3], s_shift[c + 3]), 0.f);
            }
            unsigned hi, lo;
            int b = row * AS + kc;
            cvt2tf32(v.x, hi, lo); sAh[b + 0] = hi; sAl[b + 0] = lo;
            cvt2tf32(v.y, hi, lo); sAh[b + 1] = hi; sAl[b + 1] = lo;
            cvt2tf32(v.z, hi, lo); sAh[b + 2] = hi; sAl[b + 2] = lo;
            cvt2tf32(v.w, hi, lo); sAh[b + 3] = hi; sAl[b + 3] = lo;
        }
        // B tile 16 x COUT
        #pragma unroll
        for (int f = tid; f < BKC * COUT / 4; f += 256) {
            int kr = f / (COUT / 4);
            int nc = (f % (COUT / 4)) * 4;
            float4 v = *(const float4*)&W[(size_t)(k0 + kr) * COUT + nc];
            unsigned hi, lo;
            int b = kr * BS + nc;
            cvt2tf32(v.x, hi, lo); sBh[b + 0] = hi; sBl[b + 0] = lo;
            cvt2tf32(v.y, hi, lo); sBh[b + 1] = hi; sBl[b + 1] = lo;
            cvt2tf32(v.z, hi, lo); sBh[b + 2] = hi; sBl[b + 2] = lo;
            cvt2tf32(v.w, hi, lo); sBh[b + 3] = hi; sBl[b + 3] = lo;
        }
        __syncthreads();
        #pragma unroll
        for (int ks = 0; ks < BKC; ks += 8) {
            unsigned ah[2][4], al[2][4];
            #pragma unroll
            for (int i = 0; i < 2; i++) {
                int r = wm * 32 + i * 16;
                ah[i][0] = sAh[(r + g) * AS + ks + t4];
                ah[i][1] = sAh[(r + g + 8) * AS + ks + t4];
                ah[i][2] = sAh[(r + g) * AS + ks + t4 + 4];
                ah[i][3] = sAh[(r + g + 8) * AS + ks + t4 + 4];
                al[i][0] = sAl[(r + g) * AS + ks + t4];
                al[i][1] = sAl[(r + g + 8) * AS + ks + t4];
                al[i][2] = sAl[(r + g) * AS + ks + t4 + 4];
                al[i][3] = sAl[(r + g + 8) * AS + ks + t4 + 4];
            }
            #pragma unroll
            for (int j = 0; j < NT; j++) {
                int col = wn * (COUT / 2) + j * 8 + g;
                unsigned bh0 = sBh[(ks + t4) * BS + col];
                unsigned bh1 = sBh[(ks + t4 + 4) * BS + col];
                unsigned bl0 = sBl[(ks + t4) * BS + col];
                unsigned bl1 = sBl[(ks + t4 + 4) * BS + col];
                #pragma unroll
                for (int i = 0; i < 2; i++) {
                    mma_tf32(acc[i][j], ah[i], bh0, bh1);   // hi*hi
                    mma_tf32(acc[i][j], ah[i], bl0, bl1);   // hi*lo
                    mma_tf32(acc[i][j], al[i], bh0, bh1);   // lo*hi
                }
            }
        }
        __syncthreads();
    }
    // epilogue: c0/c1 -> (row g, cols 2t,2t+1); c2/c3 -> row g+8
    #pragma unroll
    for (int i = 0; i < 2; i++) {
        int r0 = brow + wm * 32 + i * 16 + g;
        #pragma unroll
        for (int j = 0; j < NT; j++) {
            int col = wn * (COUT / 2) + j * 8 + t4 * 2;
            if (r0 < N)
                *(float2*)&out[(size_t)r0 * COUT + col] = make_float2(acc[i][j][0], acc[i][j][1]);
            if (r0 + 8 < N)
                *(float2*)&out[(size_t)(r0 + 8) * COUT + col] = make_float2(acc[i][j][2], acc[i][j][3]);
        }
    }
}

// ---------------- aggregation: out = S * act  (plain, barrier-free, warp/node) ----
template<int W>
__global__ void k_agg(const float* __restrict__ act, float* __restrict__ out, int N) {
    constexpr int V = W / 32;
    int gw   = (blockIdx.x * blockDim.x + threadIdx.x) >> 5;
    int lane = threadIdx.x & 31;
    if (gw >= N) return;

    float sn = g_selfnorm[gw];
    float acc[V];
    if constexpr (V == 4) {
        float4 tv = *(const float4*)&act[(size_t)gw * W + lane * 4];
        acc[0] = sn * tv.x; acc[1] = sn * tv.y; acc[2] = sn * tv.z; acc[3] = sn * tv.w;
    } else {
        float2 tv = *(const float2*)&act[(size_t)gw * W + lane * 2];
        acc[0] = sn * tv.x; acc[1] = sn * tv.y;
    }
    int r0 = g_rowstart[gw], r1 = g_rowstart[gw + 1];
    #pragma unroll 4
    for (int e = r0; e < r1; e++) {
        Edge ed = g_csr[e];
        float nm = ed.nm;
        if constexpr (V == 4) {
            float4 v = *(const float4*)&act[(size_t)ed.s * W + lane * 4];
            acc[0] = fmaf(nm, v.x, acc[0]); acc[1] = fmaf(nm, v.y, acc[1]);
            acc[2] = fmaf(nm, v.z, acc[2]); acc[3] = fmaf(nm, v.w, acc[3]);
        } else {
            float2 v = *(const float2*)&act[(size_t)ed.s * W + lane * 2];
            acc[0] = fmaf(nm, v.x, acc[0]); acc[1] = fmaf(nm, v.y, acc[1]);
        }
    }
    if constexpr (V == 4) {
        *(float4*)&out[(size_t)gw * W + lane * 4] = make_float4(acc[0], acc[1], acc[2], acc[3]);
    } else {
        *(float2*)&out[(size_t)gw * W + lane * 2] = make_float2(acc[0], acc[1]);
    }
}

// ---------------- BN stats + fused param computation (last-block pattern) ----------
template<int COUT>
__global__ __launch_bounds__(256) void k_bnstats(const float* __restrict__ h,
                                                 const float* __restrict__ gam,
                                                 const float* __restrict__ bet,
                                                 int N, float invN) {
    constexpr int REP = 256 / COUT;
    __shared__ float s_s[256], s_q[256];
    __shared__ bool is_last;
    int t = threadIdx.x;
    int c = t & (COUT - 1);
    int rep = t / COUT;
    int chunk = (N + gridDim.x - 1) / gridDim.x;
    int lo = blockIdx.x * chunk;
    int hi = min(lo + chunk, N);
    float s = 0.f, q = 0.f;
    for (int r = lo + rep; r < hi; r += REP) {
        float v = h[(size_t)r * COUT + c];
        s += v;
        q = fmaf(v, v, q);
    }
    s_s[t] = s; s_q[t] = q;
    __syncthreads();
    if (t < COUT) {
        #pragma unroll
        for (int w = 1; w < REP; w++) { s += s_s[t + w * COUT]; q += s_q[t + w * COUT]; }
        atomicAdd(&g_bnsum[t], s);
        atomicAdd(&g_bnsq[t],  q);
    }
    __threadfence();
    if (t == 0) {
        int v = atomicAdd(&g_ticket, 1);
        is_last = (v == (int)gridDim.x - 1);
    }
    __syncthreads();
    if (is_last) {
        if (t == 0) g_ticket = 0;
        if (t < COUT) {
            float ms = atomicAdd(&g_bnsum[t], 0.f);
            float mq = atomicAdd(&g_bnsq[t], 0.f);
            float m  = ms * invN;
            float va = mq * invN - m * m;
            float inv = rsqrtf(va + 1e-5f);
            float sc = gam[t] * inv;
            g_scale[t] = sc;
            g_shift[t] = bet[t] - m * sc;
            g_bnsum[t] = 0.f;
            g_bnsq[t]  = 0.f;
        }
    }
}

// ---------------- final BN+ReLU writing d_out (LOUT channels) ----------------
__global__ void k_bnfinal(const float* __restrict__ h, float* __restrict__ out, int total) {
    int idx = blockIdx.x * blockDim.x + threadIdx.x;
    if (idx >= total) return;
    int c = idx & (LOUT - 1);
    out[idx] = fmaxf(fmaf(h[idx], g_scale[c], g_shift[c]), 0.f);
}

// ---------------- launch ----------------
extern "C" void kernel_launch(void* const* d_in, const int* in_sizes, int n_in,
                              void* d_out, int out_size) {
    const float* x   = (const float*)d_in[0];
    const void*  ei  = d_in[1];
    const float* ew  = (const float*)d_in[2];
    const float* W0  = (const float*)d_in[3];
    const float* ga0 = (const float*)d_in[5];
    const float* be0 = (const float*)d_in[6];
    const float* W1  = (const float*)d_in[7];
    const float* ga1 = (const float*)d_in[9];
    const float* be1 = (const float*)d_in[10];
    const float* Wf  = (const float*)d_in[11];
    const float* gaf = (const float*)d_in[13];
    const float* bef = (const float*)d_in[14];
    // biases d_in[4]/[8]/[12] are dead: BN mean-subtraction cancels them exactly.

    int N = in_sizes[0] / CH;
    int E = in_sizes[2];
    float invN = 1.0f / (float)N;

    float *act_ptr = nullptr, *agg_ptr = nullptr;
    cudaGetSymbolAddress((void**)&act_ptr, g_act);
    cudaGetSymbolAddress((void**)&agg_ptr, g_agg);

    int nb_e = (E + 255) / 256;
    int nb_scan = (N + SCHUNK - 1) / SCHUNK;
    int gemm_blocks = (N + 127) / 128;
    int agg_blocks  = (N * 32 + 255) / 256;

    // preprocessing
    k_deg<<<nb_e, 256>>>(ei, ew, E);
    k_scan1<<<nb_scan, 256>>>(N);
    k_scan2<<<1, 64>>>(nb_scan);
    k_gemm<CH, false><<<gemm_blocks, 256>>>(x, W0, act_ptr, N);   // PROFILED SLOT (4th)
    k_scan3<<<nb_scan, 256>>>(N, E);
    k_fill<<<nb_e, 256>>>(ei, ew, E);

    // layer 0
    k_agg<CH><<<agg_blocks, 256>>>(act_ptr, agg_ptr, N);
    k_bnstats<CH><<<296, 256>>>(agg_ptr, ga0, be0, N, invN);

    // layer 1
    k_gemm<CH, true><<<gemm_blocks, 256>>>(agg_ptr, W1, act_ptr, N);
    k_agg<CH><<<agg_blocks, 256>>>(act_ptr, agg_ptr, N);
    k_bnstats<CH><<<296, 256>>>(agg_ptr, ga1, be1, N, invN);

    // layer 2 (64-wide agg)
    k_gemm<LOUT, true><<<gemm_blocks, 256>>>(agg_ptr, Wf, act_ptr, N);
    k_agg<LOUT><<<agg_blocks, 256>>>(act_ptr, agg_ptr, N);
    k_bnstats<LOUT><<<296, 256>>>(agg_ptr, gaf, bef, N, invN);
    k_bnfinal<<<(N * LOUT + 255) / 256, 256>>>(agg_ptr, (float*)d_out, N * LOUT);
}

// round 12
// speedup vs baseline: 1.8325x; 1.0417x over previous
#include <cuda_runtime.h>
#include <math.h>

// ---------------- problem constants ----------------
#define NMAX 50000
#define EMAX 800000
#define CH   128
#define LOUT 64
#define SCHUNK 1024   // counts per scan block
#define BKC  16       // GEMM k-chunk

// ---------------- device scratch ----------------
struct alignas(8) Edge { int s; float nm; };
__device__ float g_deg[NMAX];
__device__ float g_dis[NMAX];
__device__ float g_selfnorm[NMAX];
__device__ int   g_count[NMAX];
__device__ int   g_rowstart[NMAX + 1];
__device__ int   g_cursor[NMAX];
__device__ int   g_partial[64];
__device__ Edge  g_csr[EMAX];
__device__ float g_act[(size_t)NMAX * CH];
__device__ float g_agg[(size_t)NMAX * CH];
__device__ float g_bnsum[CH];
__device__ float g_bnsq[CH];
__device__ float g_scale[CH];
__device__ float g_shift[CH];
__device__ int   g_ticket;
// pre-split weights (tf32 hi/lo): W0 @0, W1 @16384, Wf @32768
__device__ unsigned g_Whi[128 * (128 + 128 + 64)];
__device__ unsigned g_Wlo[128 * (128 + 128 + 64)];

// ---------------- helpers ----------------
__device__ __forceinline__ bool idx_is64(const void* ei) {
    const int* w = (const int*)ei;
    return ((w[1] | w[3] | w[5] | w[7] | w[9]) == 0);
}
__device__ __forceinline__ int fetch_idx(const void* p, long long i, bool is64) {
    if (is64) return (int)((const long long*)p)[i];
    return ((const int*)p)[i];
}
__device__ __forceinline__ void cvt2tf32(float x, unsigned& hi, unsigned& lo) {
    asm("cvt.rna.tf32.f32 %0, %1;" : "=r"(hi) : "f"(x));
    float l = x - __uint_as_float(hi);
    asm("cvt.rna.tf32.f32 %0, %1;" : "=r"(lo) : "f"(l));
}
__device__ __forceinline__ void mma_tf32(float* c, const unsigned* a, unsigned b0, unsigned b1) {
    asm volatile("mma.sync.aligned.m16n8k8.row.col.f32.tf32.tf32.f32 "
        "{%0,%1,%2,%3}, {%4,%5,%6,%7}, {%8,%9}, {%0,%1,%2,%3};"
        : "+f"(c[0]), "+f"(c[1]), "+f"(c[2]), "+f"(c[3])
        : "r"(a[0]), "r"(a[1]), "r"(a[2]), "r"(a[3]), "r"(b0), "r"(b1));
}

// ---------------- weight pre-split (once per launch, all 3 layers) ----------------
__global__ void k_wsplit(const float* __restrict__ W0, const float* __restrict__ W1,
                         const float* __restrict__ Wf) {
    int i = blockIdx.x * 256 + threadIdx.x;     // 0 .. 16383
    if (i < 128 * 128) {
        unsigned hi, lo;
        cvt2tf32(W0[i], hi, lo); g_Whi[i] = hi;          g_Wlo[i] = lo;
        cvt2tf32(W1[i], hi, lo); g_Whi[16384 + i] = hi;  g_Wlo[16384 + i] = lo;
        if (i < 128 * 64) {
            cvt2tf32(Wf[i], hi, lo); g_Whi[32768 + i] = hi; g_Wlo[32768 + i] = lo;
        }
    }
}

// ---------------- degree + count accumulation ----------------
__global__ void k_deg(const void* ei, const float* __restrict__ ew, int E) {
    int e = blockIdx.x * blockDim.x + threadIdx.x;
    if (e >= E) return;
    bool is64 = idx_is64(ei);
    int d = fetch_idx(ei, (long long)E + e, is64);
    atomicAdd(&g_deg[d], ew[e]);
    atomicAdd(&g_count[d], 1);
}

// ---------------- parallel scan phases ----------------
__global__ __launch_bounds__(256) void k_scan1(int N) {
    int base = blockIdx.x * SCHUNK + threadIdx.x * 4;
    int s = 0;
    #pragma unroll
    for (int k = 0; k < 4; k++) { int i = base + k; if (i < N) s += g_count[i]; }
    #pragma unroll
    for (int o = 16; o > 0; o >>= 1) s += __shfl_down_sync(0xffffffffu, s, o);
    __shared__ int ws[8];
    if ((threadIdx.x & 31) == 0) ws[threadIdx.x >> 5] = s;
    __syncthreads();
    if (threadIdx.x < 8) {
        int v = ws[threadIdx.x];
        #pragma unroll
        for (int o = 4; o > 0; o >>= 1) v += __shfl_down_sync(0xffu, v, o, 8);
        if (threadIdx.x == 0) g_partial[blockIdx.x] = v;
    }
}

__global__ void k_scan2(int nb) {
    __shared__ int sh[64];
    int t = threadIdx.x;
    int v = (t < nb) ? g_partial[t] : 0;
    sh[t] = v;
    __syncthreads();
    #pragma unroll
    for (int o = 1; o < 64; o <<= 1) {
        int u = (t >= o) ? sh[t - o] : 0;
        __syncthreads();
        sh[t] += u;
        __syncthreads();
    }
    g_partial[t] = sh[t] - v;
}

__global__ __launch_bounds__(256) void k_scan3(int N, int E) {
    int t = threadIdx.x, lane = t & 31, w = t >> 5;
    int base = blockIdx.x * SCHUNK + t * 4;
    int c[4]; int s = 0;
    #pragma unroll
    for (int k = 0; k < 4; k++) {
        int i = base + k;
        c[k] = (i < N) ? g_count[i] : 0;
        s += c[k];
    }
    int incl = s;
    #pragma unroll
    for (int o = 1; o < 32; o <<= 1) {
        int u = __shfl_up_sync(0xffffffffu, incl, o);
        if (lane >= o) incl += u;
    }
    int wexcl = incl - s;
    __shared__ int wtot[8], woff[8];
    if (lane == 31) wtot[w] = incl;
    __syncthreads();
    if (t < 8) {
        int v = wtot[t], iv = v;
        #pragma unroll
        for (int o = 1; o < 8; o <<= 1) {
            int u = __shfl_up_sync(0xffu, iv, o, 8);
            if (t >= o) iv += u;
        }
        woff[t] = iv - v;
    }
    __syncthreads();
    int run = g_partial[blockIdx.x] + woff[w] + wexcl;
    #pragma unroll
    for (int k = 0; k < 4; k++) {
        int i = base + k;
        if (i < N) {
            g_rowstart[i] = run;
            g_cursor[i]   = run;
            run += c[k];
            g_count[i] = 0;
            float d = rsqrtf(g_deg[i] + 1.0f);
            g_dis[i] = d;
            g_selfnorm[i] = d * d;
            g_deg[i] = 0.f;
        }
    }
    if (blockIdx.x == 0 && t == 0) g_rowstart[N] = E;
}

__global__ void k_fill(const void* ei, const float* __restrict__ ew, int E) {
    int e = blockIdx.x * blockDim.x + threadIdx.x;
    if (e >= E) return;
    bool is64 = idx_is64(ei);
    int s = fetch_idx(ei, e, is64);
    int d = fetch_idx(ei, (long long)E + e, is64);
    float nm = g_dis[s] * ew[e] * g_dis[d];
    int pos = atomicAdd(&g_cursor[d], 1);
    Edge ed; ed.s = s; ed.nm = nm;
    g_csr[pos] = ed;
}

// ---------------- tf32 tensor GEMM: out = f(A)[N,128] @ W[128,COUT] ----------------
// 3-term split (hi*hi + hi*lo + lo*hi). W pre-split in g_Whi/g_Wlo (woff = layer offset).
// 8 warps 4(m) x 2(n), warp tile 32 x COUT/2, BK=16, 2 CTAs/SM.
template<int COUT, bool BN>
__global__ __launch_bounds__(256, 2) void k_gemm(const float* __restrict__ A,
                                                 int woff,
                                                 float* __restrict__ out, int N) {
    constexpr int AS = 20;          // A smem row stride (u32)
    constexpr int BS = COUT + 8;    // B smem k-row stride (u32)
    constexpr int NT = COUT / 16;   // n8 tiles per warp
    __shared__ unsigned sAh[128 * AS], sAl[128 * AS];
    __shared__ unsigned sBh[BKC * BS], sBl[BKC * BS];
    __shared__ float s_scale[128], s_shift[128];

    int tid = threadIdx.x;
    int lane = tid & 31, w = tid >> 5;
    int wm = w & 3, wn = w >> 2;
    int brow = blockIdx.x * 128;
    int g = lane >> 2, t4 = lane & 3;

    if (BN) {
        if (tid < 128) { s_scale[tid] = g_scale[tid]; s_shift[tid] = g_shift[tid]; }
        __syncthreads();
    }

    float acc[2][NT][4];
    #pragma unroll
    for (int i = 0; i < 2; i++)
        #pragma unroll
        for (int j = 0; j < NT; j++)
            #pragma unroll
            for (int q = 0; q < 4; q++) acc[i][j][q] = 0.f;

    for (int k0 = 0; k0 < 128; k0 += BKC) {
        // A tile 128 x 16: convert fp32 -> hi/lo tf32
        #pragma unroll
        for (int q = 0; q < 2; q++) {
            int f = tid + q * 256;
            int row = f >> 2;
            int kc = (f & 3) * 4;
            int gr = brow + row;
            float4 v = make_float4(0.f, 0.f, 0.f, 0.f);
            if (gr < N) v = *(const float4*)&A[(size_t)gr * 128 + k0 + kc];
            if (BN) {
                int c = k0 + kc;
                v.x = fmaxf(fmaf(v.x, s_scale[c + 0], s_shift[c + 0]), 0.f);
                v.y = fmaxf(fmaf(v.y, s_scale[c + 1], s_shift[c + 1]), 0.f);
                v.z = fmaxf(fmaf(v.z, s_scale[c + 2], s_shift[c + 2]), 0.f);
                v.w = fmaxf(fmaf(v.w, s_scale[c + 3], s_shift[c + 3]), 0.f);
            }
            unsigned hi, lo;
            int b = row * AS + kc;
            cvt2tf32(v.x, hi, lo); sAh[b + 0] = hi; sAl[b + 0] = lo;
            cvt2tf32(v.y, hi, lo); sAh[b + 1] = hi; sAl[b + 1] = lo;
            cvt2tf32(v.z, hi, lo); sAh[b + 2] = hi; sAl[b + 2] = lo;
            cvt2tf32(v.w, hi, lo); sAh[b + 3] = hi; sAl[b + 3] = lo;
        }
        // B tile 16 x COUT: plain u32 copies from pre-split weights
        #pragma unroll
        for (int f = tid; f < BKC * COUT / 4; f += 256) {
            int kr = f / (COUT / 4);
            int nc = (f % (COUT / 4)) * 4;
            int gidx = woff + (k0 + kr) * COUT + nc;
            uint4 vh = *(const uint4*)&g_Whi[gidx];
            uint4 vl = *(const uint4*)&g_Wlo[gidx];
            int b = kr * BS + nc;
            *(uint4*)&sBh[b] = vh;
            *(uint4*)&sBl[b] = vl;
        }
        __syncthreads();
        #pragma unroll
        for (int ks = 0; ks < BKC; ks += 8) {
            unsigned ah[2][4], al[2][4];
            #pragma unroll
            for (int i = 0; i < 2; i++) {
                int r = wm * 32 + i * 16;
                ah[i][0] = sAh[(r + g) * AS + ks + t4];
                ah[i][1] = sAh[(r + g + 8) * AS + ks + t4];
                ah[i][2] = sAh[(r + g) * AS + ks + t4 + 4];
                ah[i][3] = sAh[(r + g + 8) * AS + ks + t4 + 4];
                al[i][0] = sAl[(r + g) * AS + ks + t4];
                al[i][1] = sAl[(r + g + 8) * AS + ks + t4];
                al[i][2] = sAl[(r + g) * AS + ks + t4 + 4];
                al[i][3] = sAl[(r + g + 8) * AS + ks + t4 + 4];
            }
            #pragma unroll
            for (int j = 0; j < NT; j++) {
                int col = wn * (COUT / 2) + j * 8 + g;
                unsigned bh0 = sBh[(ks + t4) * BS + col];
                unsigned bh1 = sBh[(ks + t4 + 4) * BS + col];
                unsigned bl0 = sBl[(ks + t4) * BS + col];
                unsigned bl1 = sBl[(ks + t4 + 4) * BS + col];
                #pragma unroll
                for (int i = 0; i < 2; i++) {
                    mma_tf32(acc[i][j], ah[i], bh0, bh1);   // hi*hi
                    mma_tf32(acc[i][j], ah[i], bl0, bl1);   // hi*lo
                    mma_tf32(acc[i][j], al[i], bh0, bh1);   // lo*hi
                }
            }
        }
        __syncthreads();
    }
    #pragma unroll
    for (int i = 0; i < 2; i++) {
        int r0 = brow + wm * 32 + i * 16 + g;
        #pragma unroll
        for (int j = 0; j < NT; j++) {
            int col = wn * (COUT / 2) + j * 8 + t4 * 2;
            if (r0 < N)
                *(float2*)&out[(size_t)r0 * COUT + col] = make_float2(acc[i][j][0], acc[i][j][1]);
            if (r0 + 8 < N)
                *(float2*)&out[(size_t)(r0 + 8) * COUT + col] = make_float2(acc[i][j][2], acc[i][j][3]);
        }
    }
}

// ---------------- aggregation: out = S * act  (plain, barrier-free, warp/node) ----
template<int W>
__global__ void k_agg(const float* __restrict__ act, float* __restrict__ out, int N) {
    constexpr int V = W / 32;
    int gw   = (blockIdx.x * blockDim.x + threadIdx.x) >> 5;
    int lane = threadIdx.x & 31;
    if (gw >= N) return;

    float sn = g_selfnorm[gw];
    float acc[V];
    if constexpr (V == 4) {
        float4 tv = *(const float4*)&act[(size_t)gw * W + lane * 4];
        acc[0] = sn * tv.x; acc[1] = sn * tv.y; acc[2] = sn * tv.z; acc[3] = sn * tv.w;
    } else {
        float2 tv = *(const float2*)&act[(size_t)gw * W + lane * 2];
        acc[0] = sn * tv.x; acc[1] = sn * tv.y;
    }
    int r0 = g_rowstart[gw], r1 = g_rowstart[gw + 1];
    #pragma unroll 4
    for (int e = r0; e < r1; e++) {
        Edge ed = g_csr[e];
        float nm = ed.nm;
        if constexpr (V == 4) {
            float4 v = *(const float4*)&act[(size_t)ed.s * W + lane * 4];
            acc[0] = fmaf(nm, v.x, acc[0]); acc[1] = fmaf(nm, v.y, acc[1]);
            acc[2] = fmaf(nm, v.z, acc[2]); acc[3] = fmaf(nm, v.w, acc[3]);
        } else {
            float2 v = *(const float2*)&act[(size_t)ed.s * W + lane * 2];
            acc[0] = fmaf(nm, v.x, acc[0]); acc[1] = fmaf(nm, v.y, acc[1]);
        }
    }
    if constexpr (V == 4) {
        *(float4*)&out[(size_t)gw * W + lane * 4] = make_float4(acc[0], acc[1], acc[2], acc[3]);
    } else {
        *(float2*)&out[(size_t)gw * W + lane * 2] = make_float2(acc[0], acc[1]);
    }
}

// ---------------- BN stats + fused param computation (last-block pattern) ----------
template<int COUT>
__global__ __launch_bounds__(256) void k_bnstats(const float* __restrict__ h,
                                                 const float* __restrict__ gam,
                                                 const float* __restrict__ bet,
                                                 int N, float invN) {
    constexpr int REP = 256 / COUT;
    __shared__ float s_s[256], s_q[256];
    __shared__ bool is_last;
    int t = threadIdx.x;
    int c = t & (COUT - 1);
    int rep = t / COUT;
    int chunk = (N + gridDim.x - 1) / gridDim.x;
    int lo = blockIdx.x * chunk;
    int hi = min(lo + chunk, N);
    float s = 0.f, q = 0.f;
    for (int r = lo + rep; r < hi; r += REP) {
        float v = h[(size_t)r * COUT + c];
        s += v;
        q = fmaf(v, v, q);
    }
    s_s[t] = s; s_q[t] = q;
    __syncthreads();
    if (t < COUT) {
        #pragma unroll
        for (int w = 1; w < REP; w++) { s += s_s[t + w * COUT]; q += s_q[t + w * COUT]; }
        atomicAdd(&g_bnsum[t], s);
        atomicAdd(&g_bnsq[t],  q);
    }
    __threadfence();
    if (t == 0) {
        int v = atomicAdd(&g_ticket, 1);
        is_last = (v == (int)gridDim.x - 1);
    }
    __syncthreads();
    if (is_last) {
        if (t == 0) g_ticket = 0;
        if (t < COUT) {
            float ms = atomicAdd(&g_bnsum[t], 0.f);
            float mq = atomicAdd(&g_bnsq[t], 0.f);
            float m  = ms * invN;
            float va = mq * invN - m * m;
            float inv = rsqrtf(va + 1e-5f);
            float sc = gam[t] * inv;
            g_scale[t] = sc;
            g_shift[t] = bet[t] - m * sc;
            g_bnsum[t] = 0.f;
            g_bnsq[t]  = 0.f;
        }
    }
}

// ---------------- final BN+ReLU writing d_out (LOUT channels) ----------------
__global__ void k_bnfinal(const float* __restrict__ h, float* __restrict__ out, int total) {
    int idx = blockIdx.x * blockDim.x + threadIdx.x;
    if (idx >= total) return;
    int c = idx & (LOUT - 1);
    out[idx] = fmaxf(fmaf(h[idx], g_scale[c], g_shift[c]), 0.f);
}

// ---------------- launch ----------------
extern "C" void kernel_launch(void* const* d_in, const int* in_sizes, int n_in,
                              void* d_out, int out_size) {
    const float* x   = (const float*)d_in[0];
    const void*  ei  = d_in[1];
    const float* ew  = (const float*)d_in[2];
    const float* W0  = (const float*)d_in[3];
    const float* ga0 = (const float*)d_in[5];
    const float* be0 = (const float*)d_in[6];
    const float* W1  = (const float*)d_in[7];
    const float* ga1 = (const float*)d_in[9];
    const float* be1 = (const float*)d_in[10];
    const float* Wf  = (const float*)d_in[11];
    const float* gaf = (const float*)d_in[13];
    const float* bef = (const float*)d_in[14];
    // biases d_in[4]/[8]/[12] are dead: BN mean-subtraction cancels them exactly.

    int N = in_sizes[0] / CH;
    int E = in_sizes[2];
    float invN = 1.0f / (float)N;

    float *act_ptr = nullptr, *agg_ptr = nullptr;
    cudaGetSymbolAddress((void**)&act_ptr, g_act);
    cudaGetSymbolAddress((void**)&agg_ptr, g_agg);

    int nb_e = (E + 255) / 256;
    int nb_scan = (N + SCHUNK - 1) / SCHUNK;
    int gemm_blocks = (N + 127) / 128;
    int agg_blocks  = (N * 32 + 255) / 256;

    // preprocessing (+ weight pre-split)
    k_wsplit<<<64, 256>>>(W0, W1, Wf);
    k_deg<<<nb_e, 256>>>(ei, ew, E);
    k_scan1<<<nb_scan, 256>>>(N);
    k_gemm<CH, false><<<gemm_blocks, 256>>>(x, 0, act_ptr, N);    // PROFILED SLOT (4th)
    k_scan2<<<1, 64>>>(nb_scan);
    k_scan3<<<nb_scan, 256>>>(N, E);
    k_fill<<<nb_e, 256>>>(ei, ew, E);

    // layer 0
    k_agg<CH><<<agg_blocks, 256>>>(act_ptr, agg_ptr, N);
    k_bnstats<CH><<<296, 256>>>(agg_ptr, ga0, be0, N, invN);

    // layer 1
    k_gemm<CH, true><<<gemm_blocks, 256>>>(agg_ptr, 16384, act_ptr, N);
    k_agg<CH><<<agg_blocks, 256>>>(act_ptr, agg_ptr, N);
    k_bnstats<CH><<<296, 256>>>(agg_ptr, ga1, be1, N, invN);

    // layer 2 (64-wide agg)
    k_gemm<LOUT, true><<<gemm_blocks, 256>>>(agg_ptr, 32768, act_ptr, N);
    k_agg<LOUT><<<agg_blocks, 256>>>(act_ptr, agg_ptr, N);
    k_bnstats<LOUT><<<296, 256>>>(agg_ptr, gaf, bef, N, invN);
    k_bnfinal<<<(N * LOUT + 255) / 256, 256>>>(agg_ptr, (float*)d_out, N * LOUT);
}

// round 13
// speedup vs baseline: 2.0155x; 1.0999x over previous
#include <cuda_runtime.h>
#include <math.h>

// ---------------- problem constants ----------------
#define NMAX 50000
#define EMAX 800000
#define CH   128
#define LOUT 64
#define SCHUNK 1024   // counts per scan block
#define BKC  16       // GEMM k-chunk

// ---------------- device scratch ----------------
struct alignas(8) Edge { int s; float nm; };
__device__ unsigned long long g_pk[NMAX];  // packed (count<<44 | wsum*2^32); zeroed by scan3
__device__ float g_dis[NMAX];
__device__ float g_selfnorm[NMAX];
__device__ int   g_rowstart[NMAX + 1];
__device__ int   g_cursor[NMAX];
__device__ int   g_partial[64];
__device__ Edge  g_csr[EMAX];
__device__ float g_act[(size_t)NMAX * CH];
__device__ float g_agg[(size_t)NMAX * CH];
__device__ float g_bnsum[CH];
__device__ float g_bnsq[CH];
__device__ float g_scale[CH];
__device__ float g_shift[CH];
__device__ int   g_ticket;
// pre-split weights (tf32 hi/lo): W0 @0, W1 @16384, Wf @32768
__device__ unsigned g_Whi[128 * (128 + 128 + 64)];
__device__ unsigned g_Wlo[128 * (128 + 128 + 64)];

// ---------------- helpers ----------------
__device__ __forceinline__ bool idx_is64(const void* ei) {
    const int* w = (const int*)ei;
    return ((w[1] | w[3] | w[5] | w[7] | w[9]) == 0);
}
__device__ __forceinline__ int fetch_idx(const void* p, long long i, bool is64) {
    if (is64) return (int)((const long long*)p)[i];
    return ((const int*)p)[i];
}
__device__ __forceinline__ void cvt2tf32(float x, unsigned& hi, unsigned& lo) {
    asm("cvt.rna.tf32.f32 %0, %1;" : "=r"(hi) : "f"(x));
    float l = x - __uint_as_float(hi);
    asm("cvt.rna.tf32.f32 %0, %1;" : "=r"(lo) : "f"(l));
}
__device__ __forceinline__ void mma_tf32(float* c, const unsigned* a, unsigned b0, unsigned b1) {
    asm volatile("mma.sync.aligned.m16n8k8.row.col.f32.tf32.tf32.f32 "
        "{%0,%1,%2,%3}, {%4,%5,%6,%7}, {%8,%9}, {%0,%1,%2,%3};"
        : "+f"(c[0]), "+f"(c[1]), "+f"(c[2]), "+f"(c[3])
        : "r"(a[0]), "r"(a[1]), "r"(a[2]), "r"(a[3]), "r"(b0), "r"(b1));
}

// ---------------- weight pre-split ----------------
__global__ void k_wsplit(const float* __restrict__ W0, const float* __restrict__ W1,
                         const float* __restrict__ Wf) {
    int i = blockIdx.x * 256 + threadIdx.x;
    if (i < 128 * 128) {
        unsigned hi, lo;
        cvt2tf32(W0[i], hi, lo); g_Whi[i] = hi;          g_Wlo[i] = lo;
        cvt2tf32(W1[i], hi, lo); g_Whi[16384 + i] = hi;  g_Wlo[16384 + i] = lo;
        if (i < 128 * 64) {
            cvt2tf32(Wf[i], hi, lo); g_Whi[32768 + i] = hi; g_Wlo[32768 + i] = lo;
        }
    }
}

// ---------------- degree + count: single packed 64-bit atomic ----------------
__global__ void k_deg(const void* ei, const float* __restrict__ ew, int E) {
    int e = blockIdx.x * blockDim.x + threadIdx.x;
    if (e >= E) return;
    bool is64 = idx_is64(ei);
    int d = fetch_idx(ei, (long long)E + e, is64);
    unsigned long long p = (1ull << 44) |
        (unsigned long long)(ew[e] * 4294967296.0f);   // w*2^32 < 2^32 (w<1)
    atomicAdd(&g_pk[d], p);
}

// ---------------- parallel scan phases ----------------
__global__ __launch_bounds__(256) void k_scan1(int N) {
    int base = blockIdx.x * SCHUNK + threadIdx.x * 4;
    int s = 0;
    #pragma unroll
    for (int k = 0; k < 4; k++) { int i = base + k; if (i < N) s += (int)(g_pk[i] >> 44); }
    #pragma unroll
    for (int o = 16; o > 0; o >>= 1) s += __shfl_down_sync(0xffffffffu, s, o);
    __shared__ int ws[8];
    if ((threadIdx.x & 31) == 0) ws[threadIdx.x >> 5] = s;
    __syncthreads();
    if (threadIdx.x < 8) {
        int v = ws[threadIdx.x];
        #pragma unroll
        for (int o = 4; o > 0; o >>= 1) v += __shfl_down_sync(0xffu, v, o, 8);
        if (threadIdx.x == 0) g_partial[blockIdx.x] = v;
    }
}

__global__ void k_scan2(int nb) {
    __shared__ int sh[64];
    int t = threadIdx.x;
    int v = (t < nb) ? g_partial[t] : 0;
    sh[t] = v;
    __syncthreads();
    #pragma unroll
    for (int o = 1; o < 64; o <<= 1) {
        int u = (t >= o) ? sh[t - o] : 0;
        __syncthreads();
        sh[t] += u;
        __syncthreads();
    }
    g_partial[t] = sh[t] - v;
}

__global__ __launch_bounds__(256) void k_scan3(int N, int E) {
    const unsigned long long M44 = (1ull << 44) - 1ull;
    int t = threadIdx.x, lane = t & 31, w = t >> 5;
    int base = blockIdx.x * SCHUNK + t * 4;
    int c[4]; unsigned long long pk[4]; int s = 0;
    #pragma unroll
    for (int k = 0; k < 4; k++) {
        int i = base + k;
        pk[k] = (i < N) ? g_pk[i] : 0ull;
        c[k] = (int)(pk[k] >> 44);
        s += c[k];
    }
    int incl = s;
    #pragma unroll
    for (int o = 1; o < 32; o <<= 1) {
        int u = __shfl_up_sync(0xffffffffu, incl, o);
        if (lane >= o) incl += u;
    }
    int wexcl = incl - s;
    __shared__ int wtot[8], woff[8];
    if (lane == 31) wtot[w] = incl;
    __syncthreads();
    if (t < 8) {
        int v = wtot[t], iv = v;
        #pragma unroll
        for (int o = 1; o < 8; o <<= 1) {
            int u = __shfl_up_sync(0xffu, iv, o, 8);
            if (t >= o) iv += u;
        }
        woff[t] = iv - v;
    }
    __syncthreads();
    int run = g_partial[blockIdx.x] + woff[w] + wexcl;
    #pragma unroll
    for (int k = 0; k < 4; k++) {
        int i = base + k;
        if (i < N) {
            g_rowstart[i] = run;
            g_cursor[i]   = run;
            run += c[k];
            float deg = (float)(pk[k] & M44) * 0x1p-32f;
            float d = rsqrtf(deg + 1.0f);
            g_dis[i] = d;
            g_selfnorm[i] = d * d;
            g_pk[i] = 0ull;
        }
    }
    if (blockIdx.x == 0 && t == 0) g_rowstart[N] = E;
}

__global__ void k_fill(const void* ei, const float* __restrict__ ew, int E) {
    int e = blockIdx.x * blockDim.x + threadIdx.x;
    if (e >= E) return;
    bool is64 = idx_is64(ei);
    int s = fetch_idx(ei, e, is64);
    int d = fetch_idx(ei, (long long)E + e, is64);
    float nm = g_dis[s] * ew[e] * g_dis[d];
    int pos = atomicAdd(&g_cursor[d], 1);
    Edge ed; ed.s = s; ed.nm = nm;
    g_csr[pos] = ed;
}

// ---------------- pipelined tf32 tensor GEMM: out = f(A)[N,128] @ W[128,COUT] ------
// 3-term split. A: reg-prefetch + double-buffered smem. B: cp.async, triple-buffered.
// One barrier per k-chunk. Dynamic smem. 2 CTAs/SM.
template<int COUT, bool BN>
__global__ __launch_bounds__(256, 2) void k_gemm(const float* __restrict__ A, int woff,
                                                 float* __restrict__ out, int N) {
    constexpr int AS = 20, BS = COUT + 8, NT = COUT / 16;
    constexpr int ABUF = 128 * AS;
    constexpr int BBUF = BKC * BS;
    constexpr int BITER = (BKC * COUT / 4) / 256;   // 2 (COUT=128) or 1 (COUT=64)
    extern __shared__ unsigned smem[];
    unsigned* sA_h = smem;
    unsigned* sA_l = smem + 2 * ABUF;
    unsigned* sB_h = smem + 4 * ABUF;
    unsigned* sB_l = smem + 4 * ABUF + 3 * BBUF;
    float* s_scale = (float*)(smem + 4 * ABUF + 6 * BBUF);
    float* s_shift = s_scale + 128;

    int tid = threadIdx.x;
    int lane = tid & 31, w = tid >> 5;
    int wm = w & 3, wn = w >> 2;
    int brow = blockIdx.x * 128;
    int g = lane >> 2, t4 = lane & 3;

    if (BN) {
        if (tid < 128) { s_scale[tid] = g_scale[tid]; s_shift[tid] = g_shift[tid]; }
        __syncthreads();
    }

    // A prefetch addressing (2 float4 per thread per chunk)
    int f1 = tid + 256;
    int row0 = tid >> 2, kc0 = (tid & 3) * 4;
    int row1 = f1 >> 2,  kc1 = (f1 & 3) * 4;
    int gr0 = brow + row0, gr1 = brow + row1;
    float4 rA0, rA1;

    auto prefA = [&](int c) {
        rA0 = (gr0 < N) ? *(const float4*)&A[(size_t)gr0 * 128 + c * BKC + kc0]
                        : make_float4(0.f, 0.f, 0.f, 0.f);
        rA1 = (gr1 < N) ? *(const float4*)&A[(size_t)gr1 * 128 + c * BKC + kc1]
                        : make_float4(0.f, 0.f, 0.f, 0.f);
    };
    auto cvtstoreA = [&](int c, int buf) {
        unsigned* dh = sA_h + buf * ABUF;
        unsigned* dl = sA_l + buf * ABUF;
        #pragma unroll
        for (int q = 0; q < 2; q++) {
            float4 v = q ? rA1 : rA0;
            int row = q ? row1 : row0;
            int kc  = q ? kc1 : kc0;
            if (BN) {
                int cb = c * BKC + kc;
                v.x = fmaxf(fmaf(v.x, s_scale[cb + 0], s_shift[cb + 0]), 0.f);
                v.y = fmaxf(fmaf(v.y, s_scale[cb + 1], s_shift[cb + 1]), 0.f);
                v.z = fmaxf(fmaf(v.z, s_scale[cb + 2], s_shift[cb + 2]), 0.f);
                v.w = fmaxf(fmaf(v.w, s_scale[cb + 3], s_shift[cb + 3]), 0.f);
            }
            unsigned hi, lo;
            int b = row * AS + kc;
            cvt2tf32(v.x, hi, lo); dh[b + 0] = hi; dl[b + 0] = lo;
            cvt2tf32(v.y, hi, lo); dh[b + 1] = hi; dl[b + 1] = lo;
            cvt2tf32(v.z, hi, lo); dh[b + 2] = hi; dl[b + 2] = lo;
            cvt2tf32(v.w, hi, lo); dh[b + 3] = hi; dl[b + 3] = lo;
        }
    };
    auto loadB = [&](int c, int buf) {
        #pragma unroll
        for (int it = 0; it < BITER; it++) {
            int f = tid + it * 256;
            int kr = f / (COUT / 4);
            int nc = (f % (COUT / 4)) * 4;
            int gidx = woff + (c * BKC + kr) * COUT + nc;
            unsigned dh = (unsigned)__cvta_generic_to_shared(sB_h + buf * BBUF + kr * BS + nc);
            unsigned dl = (unsigned)__cvta_generic_to_shared(sB_l + buf * BBUF + kr * BS + nc);
            asm volatile("cp.async.cg.shared.global [%0], [%1], 16;" :: "r"(dh), "l"(&g_Whi[gidx]));
            asm volatile("cp.async.cg.shared.global [%0], [%1], 16;" :: "r"(dl), "l"(&g_Wlo[gidx]));
        }
        asm volatile("cp.async.commit_group;");
    };

    float acc[2][NT][4];
    #pragma unroll
    for (int i = 0; i < 2; i++)
        #pragma unroll
        for (int j = 0; j < NT; j++)
            #pragma unroll
            for (int q = 0; q < 4; q++) acc[i][j][q] = 0.f;

    // prologue: chunk0 in smem, chunk1 staged (A in regs, B in flight)
    prefA(0);
    loadB(0, 0);
    loadB(1, 1);
    cvtstoreA(0, 0);
    prefA(1);
    asm volatile("cp.async.wait_group 1;");
    __syncthreads();

    #pragma unroll 1
    for (int c = 0; c < 8; c++) {
        const unsigned* Ah = sA_h + (c & 1) * ABUF;
        const unsigned* Al = sA_l + (c & 1) * ABUF;
        const unsigned* Bh = sB_h + (c % 3) * BBUF;
        const unsigned* Bl = sB_l + (c % 3) * BBUF;
        #pragma unroll
        for (int ks = 0; ks < BKC; ks += 8) {
            unsigned ah[2][4], al[2][4];
            #pragma unroll
            for (int i = 0; i < 2; i++) {
                int r = wm * 32 + i * 16;
                ah[i][0] = Ah[(r + g) * AS + ks + t4];
                ah[i][1] = Ah[(r + g + 8) * AS + ks + t4];
                ah[i][2] = Ah[(r + g) * AS + ks + t4 + 4];
                ah[i][3] = Ah[(r + g + 8) * AS + ks + t4 + 4];
                al[i][0] = Al[(r + g) * AS + ks + t4];
                al[i][1] = Al[(r + g + 8) * AS + ks + t4];
                al[i][2] = Al[(r + g) * AS + ks + t4 + 4];
                al[i][3] = Al[(r + g + 8) * AS + ks + t4 + 4];
            }
            #pragma unroll
            for (int j = 0; j < NT; j++) {
                int col = wn * (COUT / 2) + j * 8 + g;
                unsigned bh0 = Bh[(ks + t4) * BS + col];
                unsigned bh1 = Bh[(ks + t4 + 4) * BS + col];
                unsigned bl0 = Bl[(ks + t4) * BS + col];
                unsigned bl1 = Bl[(ks + t4 + 4) * BS + col];
                #pragma unroll
                for (int i = 0; i < 2; i++) {
                    mma_tf32(acc[i][j], ah[i], bh0, bh1);   // hi*hi
                    mma_tf32(acc[i][j], ah[i], bl0, bl1);   // hi*lo
                    mma_tf32(acc[i][j], al[i], bh0, bh1);   // lo*hi
                }
            }
        }
        if (c < 7) {
            cvtstoreA(c + 1, (c + 1) & 1);          // stage A chunk c+1 into smem
            if (c < 6) {
                prefA(c + 2);                        // A chunk c+2 -> regs
                loadB(c + 2, (c + 2) % 3);           // B chunk c+2 -> smem (async)
                asm volatile("cp.async.wait_group 1;");   // B chunk c+1 complete
            } else {
                asm volatile("cp.async.wait_group 0;");   // B chunk 7 complete
            }
            __syncthreads();
        }
    }

    #pragma unroll
    for (int i = 0; i < 2; i++) {
        int r0 = brow + wm * 32 + i * 16 + g;
        #pragma unroll
        for (int j = 0; j < NT; j++) {
            int col = wn * (COUT / 2) + j * 8 + t4 * 2;
            if (r0 < N)
                *(float2*)&out[(size_t)r0 * COUT + col] = make_float2(acc[i][j][0], acc[i][j][1]);
            if (r0 + 8 < N)
                *(float2*)&out[(size_t)(r0 + 8) * COUT + col] = make_float2(acc[i][j][2], acc[i][j][3]);
        }
    }
}

// ---------------- aggregation: out = S * act  (plain, barrier-free, warp/node) ----
template<int W>
__global__ void k_agg(const float* __restrict__ act, float* __restrict__ out, int N) {
    constexpr int V = W / 32;
    int gw   = (blockIdx.x * blockDim.x + threadIdx.x) >> 5;
    int lane = threadIdx.x & 31;
    if (gw >= N) return;

    float sn = g_selfnorm[gw];
    float acc[V];
    if constexpr (V == 4) {
        float4 tv = *(const float4*)&act[(size_t)gw * W + lane * 4];
        acc[0] = sn * tv.x; acc[1] = sn * tv.y; acc[2] = sn * tv.z; acc[3] = sn * tv.w;
    } else {
        float2 tv = *(const float2*)&act[(size_t)gw * W + lane * 2];
        acc[0] = sn * tv.x; acc[1] = sn * tv.y;
    }
    int r0 = g_rowstart[gw], r1 = g_rowstart[gw + 1];
    #pragma unroll 4
    for (int e = r0; e < r1; e++) {
        Edge ed = g_csr[e];
        float nm = ed.nm;
        if constexpr (V == 4) {
            float4 v = *(const float4*)&act[(size_t)ed.s * W + lane * 4];
            acc[0] = fmaf(nm, v.x, acc[0]); acc[1] = fmaf(nm, v.y, acc[1]);
            acc[2] = fmaf(nm, v.z, acc[2]); acc[3] = fmaf(nm, v.w, acc[3]);
        } else {
            float2 v = *(const float2*)&act[(size_t)ed.s * W + lane * 2];
            acc[0] = fmaf(nm, v.x, acc[0]); acc[1] = fmaf(nm, v.y, acc[1]);
        }
    }
    if constexpr (V == 4) {
        *(float4*)&out[(size_t)gw * W + lane * 4] = make_float4(acc[0], acc[1], acc[2], acc[3]);
    } else {
        *(float2*)&out[(size_t)gw * W + lane * 2] = make_float2(acc[0], acc[1]);
    }
}

// ---------------- BN stats + fused param computation (last-block pattern) ----------
template<int COUT>
__global__ __launch_bounds__(256) void k_bnstats(const float* __restrict__ h,
                                                 const float* __restrict__ gam,
                                                 const float* __restrict__ bet,
                                                 int N, float invN) {
    constexpr int REP = 256 / COUT;
    __shared__ float s_s[256], s_q[256];
    __shared__ bool is_last;
    int t = threadIdx.x;
    int c = t & (COUT - 1);
    int rep = t / COUT;
    int chunk = (N + gridDim.x - 1) / gridDim.x;
    int lo = blockIdx.x * chunk;
    int hi = min(lo + chunk, N);
    float s = 0.f, q = 0.f;
    for (int r = lo + rep; r < hi; r += REP) {
        float v = h[(size_t)r * COUT + c];
        s += v;
        q = fmaf(v, v, q);
    }
    s_s[t] = s; s_q[t] = q;
    __syncthreads();
    if (t < COUT) {
        #pragma unroll
        for (int w = 1; w < REP; w++) { s += s_s[t + w * COUT]; q += s_q[t + w * COUT]; }
        atomicAdd(&g_bnsum[t], s);
        atomicAdd(&g_bnsq[t],  q);
    }
    __threadfence();
    if (t == 0) {
        int v = atomicAdd(&g_ticket, 1);
        is_last = (v == (int)gridDim.x - 1);
    }
    __syncthreads();
    if (is_last) {
        if (t == 0) g_ticket = 0;
        if (t < COUT) {
            float ms = atomicAdd(&g_bnsum[t], 0.f);
            float mq = atomicAdd(&g_bnsq[t], 0.f);
            float m  = ms * invN;
            float va = mq * invN - m * m;
            float inv = rsqrtf(va + 1e-5f);
            float sc = gam[t] * inv;
            g_scale[t] = sc;
            g_shift[t] = bet[t] - m * sc;
            g_bnsum[t] = 0.f;
            g_bnsq[t]  = 0.f;
        }
    }
}

// ---------------- final BN+ReLU writing d_out (LOUT channels) ----------------
__global__ void k_bnfinal(const float* __restrict__ h, float* __restrict__ out, int total) {
    int idx = blockIdx.x * blockDim.x + threadIdx.x;
    if (idx >= total) return;
    int c = idx & (LOUT - 1);
    out[idx] = fmaxf(fmaf(h[idx], g_scale[c], g_shift[c]), 0.f);
}

// ---------------- launch ----------------
extern "C" void kernel_launch(void* const* d_in, const int* in_sizes, int n_in,
                              void* d_out, int out_size) {
    const float* x   = (const float*)d_in[0];
    const void*  ei  = d_in[1];
    const float* ew  = (const float*)d_in[2];
    const float* W0  = (const float*)d_in[3];
    const float* ga0 = (const float*)d_in[5];
    const float* be0 = (const float*)d_in[6];
    const float* W1  = (const float*)d_in[7];
    const float* ga1 = (const float*)d_in[9];
    const float* be1 = (const float*)d_in[10];
    const float* Wf  = (const float*)d_in[11];
    const float* gaf = (const float*)d_in[13];
    const float* bef = (const float*)d_in[14];
    // biases d_in[4]/[8]/[12] are dead: BN mean-subtraction cancels them exactly.

    int N = in_sizes[0] / CH;
    int E = in_sizes[2];
    float invN = 1.0f / (float)N;

    float *act_ptr = nullptr, *agg_ptr = nullptr;
    cudaGetSymbolAddress((void**)&act_ptr, g_act);
    cudaGetSymbolAddress((void**)&agg_ptr, g_agg);

    // dynamic smem: COUT=128 -> (4*2560 + 6*2176 + 256)*4 = 94208 B
    //               COUT=64  -> (4*2560 + 6*1152 + 256)*4 = 69632 B
    const int SM128 = 94208, SM64 = 69632;
    cudaFuncSetAttribute(k_gemm<CH, false>, cudaFuncAttributeMaxDynamicSharedMemorySize, SM128);
    cudaFuncSetAttribute(k_gemm<CH, true>,  cudaFuncAttributeMaxDynamicSharedMemorySize, SM128);
    cudaFuncSetAttribute(k_gemm<LOUT, true>, cudaFuncAttributeMaxDynamicSharedMemorySize, SM64);

    int nb_e = (E + 255) / 256;
    int nb_scan = (N + SCHUNK - 1) / SCHUNK;
    int gemm_blocks = (N + 127) / 128;
    int agg_blocks  = (N * 32 + 255) / 256;

    // preprocessing (+ weight pre-split)
    k_wsplit<<<64, 256>>>(W0, W1, Wf);
    k_deg<<<nb_e, 256>>>(ei, ew, E);
    k_scan1<<<nb_scan, 256>>>(N);
    k_gemm<CH, false><<<gemm_blocks, 256, SM128>>>(x, 0, act_ptr, N);   // PROFILED SLOT (4th)
    k_scan2<<<1, 64>>>(nb_scan);
    k_scan3<<<nb_scan, 256>>>(N, E);
    k_fill<<<nb_e, 256>>>(ei, ew, E);

    // layer 0
    k_agg<CH><<<agg_blocks, 256>>>(act_ptr, agg_ptr, N);
    k_bnstats<CH><<<296, 256>>>(agg_ptr, ga0, be0, N, invN);

    // layer 1
    k_gemm<CH, true><<<gemm_blocks, 256, SM128>>>(agg_ptr, 16384, act_ptr, N);
    k_agg<CH><<<agg_blocks, 256>>>(act_ptr, agg_ptr, N);
    k_bnstats<CH><<<296, 256>>>(agg_ptr, ga1, be1, N, invN);

    // layer 2 (64-wide agg)
    k_gemm<LOUT, true><<<gemm_blocks, 256, SM64>>>(agg_ptr, 32768, act_ptr, N);
    k_agg<LOUT><<<agg_blocks, 256>>>(act_ptr, agg_ptr, N);
    k_bnstats<LOUT><<<296, 256>>>(agg_ptr, gaf, bef, N, invN);
    k_bnfinal<<<(N * LOUT + 255) / 256, 256>>>(agg_ptr, (float*)d_out, N * LOUT);
}